// round 13
// baseline (speedup 1.0000x reference)
#include <cuda_runtime.h>
#include <cuda_fp16.h>
#include <cstdint>

#define Bq 8
#define Sq 512
#define Dm 1024
#define DKh 64
#define FFd 4096
#define NL 4
#define Mrows 4096

// ---------------- scratch ----------------------------------------------------
__device__ float  g_x  [(size_t)Mrows*Dm];
__device__ __half g_xh [(size_t)Mrows*Dm];
__device__ __half g_p16[(size_t)Bq*Sq*Sq];
__device__ __half g_q16[(size_t)Mrows*DKh];
__device__ __half g_k16[(size_t)Mrows*DKh];
__device__ __half g_vt [(size_t)Bq*DKh*Sq];
__device__ __half g_hd16[(size_t)Mrows*DKh];
__device__ __half g_h16[(size_t)Mrows*FFd];
__device__ __half g_wqh[(size_t)NL*192*Dm];
__device__ __half g_w1h[(size_t)NL*FFd*Dm];
__device__ __half g_w2h[(size_t)NL*Dm*FFd];
__device__ __half g_woh[(size_t)NL*Dm*DKh];
__device__ float  g_bqkv[NL*192];

// ---------------- helpers -----------------------------------------------------
__device__ __forceinline__ uint32_t smem_u32(const void* p){
    uint32_t a;
    asm("{ .reg .u64 t; cvta.to.shared.u64 t, %1; cvt.u32.u64 %0, t; }":"=r"(a):"l"(p));
    return a;
}
__device__ __forceinline__ void cpa16(uint32_t d, const void* s){
    asm volatile("cp.async.cg.shared.global [%0], [%1], 16;"::"r"(d),"l"(s));
}
__device__ __forceinline__ void cpa_commit(){ asm volatile("cp.async.commit_group;":::"memory"); }
__device__ __forceinline__ void cpa_wait1(){ asm volatile("cp.async.wait_group 1;":::"memory"); }
__device__ __forceinline__ void cpa_wait0(){ asm volatile("cp.async.wait_group 0;":::"memory"); }

#define LDMX4(r, addr) \
    asm volatile("ldmatrix.sync.aligned.m8n8.x4.shared.b16 {%0,%1,%2,%3}, [%4];" \
        : "=r"((r)[0]),"=r"((r)[1]),"=r"((r)[2]),"=r"((r)[3]) : "r"(addr))

#define HMMA16816(c, a, b0v, b1v) \
    asm volatile("mma.sync.aligned.m16n8k16.row.col.f32.f16.f16.f32 " \
        "{%0,%1,%2,%3}, {%4,%5,%6,%7}, {%8,%9}, {%0,%1,%2,%3};" \
        : "+f"((c)[0]),"+f"((c)[1]),"+f"((c)[2]),"+f"((c)[3]) \
        : "r"((a)[0]),"r"((a)[1]),"r"((a)[2]),"r"((a)[3]), "r"(b0v),"r"(b1v))

// ---------------- fp16 HMMA GEMM  C = epi(alpha * A @ B^T) ---------------------
// 512 threads, warp grid 4x4. A: [M,K] fp16 (batch stride sA). B: [N,K] fp16
// (stride sB). K%64==0, M%128==0, BN_%64==0.
#define TCE_QKV   0   // +bias; route fp16 to Q / K / V^T (blockIdx.x selects)
#define TCE_PV    2   // fp16 Oh only
#define TCE_RELU  3   // +bias, relu -> fp16 Oh
#define TCE_BN    4   // +bias+resid, BN -> fp32 C (+fp16 Oh if WB16)
#define TCE_SMAX  5   // fused softmax(alpha*scores) -> fp16 Oh (needs BN_=512)

template <int BN_, int EPI, bool WB16>
__global__ void __launch_bounds__(512, 1)
hgemm(const __half* __restrict__ A, const __half* __restrict__ B,
      const float* __restrict__ bias, int K, float alpha,
      float* __restrict__ Cf, int ldc,
      __half* __restrict__ Oh, __half* __restrict__ O2, __half* __restrict__ O3,
      long sA, long sB, long sC,
      const float* __restrict__ resid,
      const float* __restrict__ gamma, const float* __restrict__ beta,
      const float* __restrict__ mean,  const float* __restrict__ var)
{
    extern __shared__ __align__(1024) char smem[];
    constexpr int STG = 16384 + BN_*128;     // A(16K) + B per stage
    constexpr int WN  = BN_/4;               // warp n-width (warps 4x4)
    constexpr int NP  = WN/16;
    constexpr int NT  = WN/8;

    A += (size_t)blockIdx.z * sA;
    B += (size_t)blockIdx.z * sB;
    if (Cf) Cf += (size_t)blockIdx.z * sC;
    if (EPI == TCE_PV || EPI == TCE_SMAX) Oh += (size_t)blockIdx.z * sC;

    const uint32_t sb = smem_u32(smem);
    const int tid = threadIdx.x, wid = tid>>5, lane = tid&31;
    const int m0 = blockIdx.y*128, n0 = blockIdx.x*BN_;
    const int wm = (wid>>2)*32,    wn = (wid&3)*WN;

    const int l15 = lane & 15, sg = lane >> 4;
    const int rA = wm + l15, rB = wn + l15;
    const uint32_t baseA = (uint32_t)rA * 128;
    const uint32_t baseB = (uint32_t)rB * 128;
    const uint32_t xorA  = ((uint32_t)(rA & 7)) << 4;
    const uint32_t xorB  = ((uint32_t)(rB & 7)) << 4;
    const uint32_t sgo   = ((uint32_t)sg) << 4;

    float acc[2][NT][4];
#pragma unroll
    for (int mt=0;mt<2;mt++)
#pragma unroll
        for (int nt=0;nt<NT;nt++)
#pragma unroll
            for (int q=0;q<4;q++) acc[mt][nt][q]=0.f;

    auto load_chunk = [&](int ck, int s){
        const int ko = ck << 6;
        const uint32_t aA = sb + s*STG;
        const uint32_t aB = aA + 16384;
#pragma unroll
        for (int i = 0; i < 2; i++) {
            int idx = tid + (i<<9); int r = idx>>3, seg = idx&7;
            uint32_t off = (r<<7)+(seg<<4), sw = off ^ ((off>>3)&0x70);
            size_t g = (size_t)(m0+r)*K + ko + (seg<<3);
            cpa16(aA+sw, A+g);
        }
#pragma unroll
        for (int i = 0; i < BN_/64; i++) {
            int idx = tid + (i<<9); int r = idx>>3, seg = idx&7;
            uint32_t off = (r<<7)+(seg<<4), sw = off ^ ((off>>3)&0x70);
            size_t g = (size_t)(n0+r)*K + ko + (seg<<3);
            cpa16(aB+sw, B+g);
        }
    };

    const int NC = K >> 6;
    load_chunk(0, 0);
    cpa_commit();

    for (int c = 0; c < NC; c++) {
        if (c+1 < NC) { load_chunk(c+1, (c+1)&1); cpa_commit(); cpa_wait1(); }
        else          { cpa_wait0(); }
        __syncthreads();

        const uint32_t aA = sb + (c&1)*STG;
        const uint32_t aB = aA + 16384;
#pragma unroll
        for (int ks = 0; ks < 4; ks++) {
            const uint32_t cA = (sgo | ((uint32_t)ks << 5)) ^ xorA;
            const uint32_t cB = (sgo | ((uint32_t)ks << 5)) ^ xorB;
            uint32_t af[2][4], bf[NP][4];
#pragma unroll
            for (int mt=0;mt<2;mt++) LDMX4(af[mt], aA + baseA + mt*2048 + cA);
#pragma unroll
            for (int np=0;np<NP;np++) LDMX4(bf[np], aB + baseB + np*2048 + cB);
#pragma unroll
            for (int mt=0;mt<2;mt++)
#pragma unroll
                for (int np=0;np<NP;np++) {
                    HMMA16816(acc[mt][2*np],   af[mt], bf[np][0], bf[np][2]);
                    HMMA16816(acc[mt][2*np+1], af[mt], bf[np][1], bf[np][3]);
                }
        }
        __syncthreads();
    }

    // ---- epilogue ----
    const int rb = m0 + wm + (lane>>2);
    const int cb = n0 + wn + (lane&3)*2;

    if constexpr (EPI == TCE_SMAX) {
        // fused softmax over the full 512-col row; rows within a quad, 4 n-warps
        float* sred = (float*)smem;            // [128][4] max
        float* ssum = (float*)(smem + 2048);   // [128][4] sum
        const int wq = wid & 3;
        const int rloc = wm + (lane>>2);

#pragma unroll
        for (int mt=0;mt<2;mt++)
#pragma unroll
            for (int nt=0;nt<NT;nt++)
#pragma unroll
                for (int q=0;q<4;q++) acc[mt][nt][q] *= alpha;

        float lmax[2][2] = {{-1e30f,-1e30f},{-1e30f,-1e30f}};
#pragma unroll
        for (int mt=0;mt<2;mt++)
#pragma unroll
            for (int nt=0;nt<NT;nt++) {
                lmax[mt][0] = fmaxf(lmax[mt][0], fmaxf(acc[mt][nt][0], acc[mt][nt][1]));
                lmax[mt][1] = fmaxf(lmax[mt][1], fmaxf(acc[mt][nt][2], acc[mt][nt][3]));
            }
#pragma unroll
        for (int o=1;o<4;o<<=1)
#pragma unroll
            for (int mt=0;mt<2;mt++)
#pragma unroll
                for (int h=0;h<2;h++)
                    lmax[mt][h] = fmaxf(lmax[mt][h], __shfl_xor_sync(0xffffffffu, lmax[mt][h], o));
        if ((lane&3)==0)
#pragma unroll
            for (int mt=0;mt<2;mt++)
#pragma unroll
                for (int h=0;h<2;h++)
                    sred[(rloc + mt*16 + h*8)*4 + wq] = lmax[mt][h];
        __syncthreads();
        float gmax[2][2];
#pragma unroll
        for (int mt=0;mt<2;mt++)
#pragma unroll
            for (int h=0;h<2;h++) {
                int rr = rloc + mt*16 + h*8;
                gmax[mt][h] = fmaxf(fmaxf(sred[rr*4+0], sred[rr*4+1]),
                                    fmaxf(sred[rr*4+2], sred[rr*4+3]));
            }
        float ls[2][2] = {{0.f,0.f},{0.f,0.f}};
#pragma unroll
        for (int mt=0;mt<2;mt++)
#pragma unroll
            for (int nt=0;nt<NT;nt++) {
                acc[mt][nt][0] = __expf(acc[mt][nt][0] - gmax[mt][0]);
                acc[mt][nt][1] = __expf(acc[mt][nt][1] - gmax[mt][0]);
                acc[mt][nt][2] = __expf(acc[mt][nt][2] - gmax[mt][1]);
                acc[mt][nt][3] = __expf(acc[mt][nt][3] - gmax[mt][1]);
                ls[mt][0] += acc[mt][nt][0] + acc[mt][nt][1];
                ls[mt][1] += acc[mt][nt][2] + acc[mt][nt][3];
            }
#pragma unroll
        for (int o=1;o<4;o<<=1)
#pragma unroll
            for (int mt=0;mt<2;mt++)
#pragma unroll
                for (int h=0;h<2;h++)
                    ls[mt][h] += __shfl_xor_sync(0xffffffffu, ls[mt][h], o);
        if ((lane&3)==0)
#pragma unroll
            for (int mt=0;mt<2;mt++)
#pragma unroll
                for (int h=0;h<2;h++)
                    ssum[(rloc + mt*16 + h*8)*4 + wq] = ls[mt][h];
        __syncthreads();
        float inv[2][2];
#pragma unroll
        for (int mt=0;mt<2;mt++)
#pragma unroll
            for (int h=0;h<2;h++) {
                int rr = rloc + mt*16 + h*8;
                inv[mt][h] = 1.f / (ssum[rr*4+0]+ssum[rr*4+1]+ssum[rr*4+2]+ssum[rr*4+3]);
            }
#pragma unroll
        for (int mt=0;mt<2;mt++)
#pragma unroll
            for (int nt=0;nt<NT;nt++) {
                const int col = cb + nt*8;
                *(__half2*)(Oh + (size_t)(rb+mt*16)*ldc + col) = __halves2half2(
                    __float2half_rn(acc[mt][nt][0]*inv[mt][0]),
                    __float2half_rn(acc[mt][nt][1]*inv[mt][0]));
                *(__half2*)(Oh + (size_t)(rb+mt*16+8)*ldc + col) = __halves2half2(
                    __float2half_rn(acc[mt][nt][2]*inv[mt][1]),
                    __float2half_rn(acc[mt][nt][3]*inv[mt][1]));
            }
        return;
    } else {
        auto epi = [&](int row, int col, float v0, float v1){
            if (EPI == TCE_PV) {
                *(__half2*)(Oh + (size_t)row*ldc + col) =
                    __halves2half2(__float2half_rn(v0), __float2half_rn(v1));
                return;
            }
            v0 += bias[col]; v1 += bias[col+1];
            if (EPI == TCE_QKV) {
                __half h0 = __float2half_rn(v0), h1 = __float2half_rn(v1);
                if (blockIdx.x < 2) {
                    __half* dst = (blockIdx.x == 0) ? Oh : O2;
                    *(__half2*)(dst + (size_t)row*DKh + (col & 63)) = __halves2half2(h0, h1);
                } else {
                    int b = row >> 9, mi = row & 511;
                    O3[((size_t)b*DKh + (col-128))*Sq + mi] = h0;
                    O3[((size_t)b*DKh + (col-127))*Sq + mi] = h1;
                }
                return;
            }
            if (EPI == TCE_RELU) { v0 = fmaxf(v0, 0.f); v1 = fmaxf(v1, 0.f); }
            if (EPI == TCE_BN) {
                float2 rs = *(const float2*)(resid + (size_t)row*ldc + col);
                v0 += rs.x; v1 += rs.y;
                v0 = gamma[col]  *(v0 - mean[col])  *rsqrtf(var[col]  +1e-3f) + beta[col];
                v1 = gamma[col+1]*(v1 - mean[col+1])*rsqrtf(var[col+1]+1e-3f) + beta[col+1];
            }
            if (EPI != TCE_RELU)
                *(float2*)(Cf + (size_t)row*ldc + col) = make_float2(v0, v1);
            if (WB16 || EPI == TCE_RELU)
                *(__half2*)(Oh + (size_t)row*ldc + col) =
                    __halves2half2(__float2half_rn(v0), __float2half_rn(v1));
        };

#pragma unroll
        for (int mt=0;mt<2;mt++)
#pragma unroll
            for (int nt=0;nt<NT;nt++) {
                const int col = cb + nt*8;
                epi(rb + mt*16,     col, acc[mt][nt][0], acc[mt][nt][1]);
                epi(rb + mt*16 + 8, col, acc[mt][nt][2], acc[mt][nt][3]);
            }
    }
}

// ---------------- weight transpose to fp16: in[K,N] -> out[N,K] ----------------
__global__ void whalf(const float* __restrict__ in, int K, int N,
                      __half* __restrict__ oh)
{
    __shared__ float t[32][33];
    const int k0 = blockIdx.x*32, n0 = blockIdx.y*32;
    const int tx = threadIdx.x, ty = threadIdx.y;
#pragma unroll
    for (int i = ty; i < 32; i += 8)
        t[i][tx] = in[(size_t)(k0+i)*N + n0 + tx];
    __syncthreads();
#pragma unroll
    for (int i = ty; i < 32; i += 8)
        oh[(size_t)(n0+i)*K + k0 + tx] = __float2half_rn(t[tx][i]);
}

__global__ void whalf_qkv(const float* __restrict__ wq, const float* __restrict__ wk,
                          const float* __restrict__ wv, __half* __restrict__ oh)
{
    __shared__ float t[32][33];
    const float* in = (blockIdx.z == 0) ? wq : (blockIdx.z == 1) ? wk : wv;
    __half* ohp = oh + (size_t)blockIdx.z*DKh*Dm;
    const int k0 = blockIdx.x*32, n0 = blockIdx.y*32;
    const int tx = threadIdx.x, ty = threadIdx.y;
#pragma unroll
    for (int i = ty; i < 32; i += 8)
        t[i][tx] = in[(size_t)(k0+i)*DKh + n0 + tx];
    __syncthreads();
#pragma unroll
    for (int i = ty; i < 32; i += 8)
        ohp[(size_t)(n0+i)*Dm + k0 + tx] = __float2half_rn(t[tx][i]);
}

__global__ void biaspack(const float* bq, const float* bk, const float* bv, float* o)
{
    int t = threadIdx.x + blockIdx.x*256;
    if (t >= NL*192) return;
    int l = t/192, j = t%192;
    o[t] = (j < 64) ? bq[l*64+j] : (j < 128) ? bk[l*64+j-64] : bv[l*64+j-128];
}

// ---------------- embed + fp16 ------------------------------------------------
__global__ void embed_k(const int* __restrict__ seq, const float* __restrict__ emb,
                        const float* __restrict__ pes, float* __restrict__ x,
                        __half* __restrict__ xh)
{
    size_t idx = (size_t)blockIdx.x*256 + threadIdx.x;
    int d = (int)(idx & (Dm-1));
    size_t bs = idx >> 10;
    int s = (int)(bs & (Sq-1));
    float v = emb[(size_t)seq[bs]*Dm + d] + pes[(size_t)s*Dm];
    x[idx] = v;
    xh[idx] = __float2half_rn(v);
}

// ---------------- host ----------------------------------------------------------
static const int SM64  = 2*(16384 + 64*128);     // 49152
static const int SM128 = 2*(16384 + 128*128);    // 65536
static const int SMS   = 16384 + 512*128;        // 81920 (single stage, K=64)

extern "C" void kernel_launch(void* const* d_in, const int* in_sizes, int n_in,
                              void* d_out, int out_size)
{
    const int*   seq = (const int*)  d_in[0];
    const float* emb = (const float*)d_in[1];
    const float* pes = (const float*)d_in[2];
    const float* wq  = (const float*)d_in[3];
    const float* bqp = (const float*)d_in[4];
    const float* wk  = (const float*)d_in[5];
    const float* bkp = (const float*)d_in[6];
    const float* wv  = (const float*)d_in[7];
    const float* bvp = (const float*)d_in[8];
    const float* wo  = (const float*)d_in[9];
    const float* bo  = (const float*)d_in[10];
    const float* ag  = (const float*)d_in[11];
    const float* ab  = (const float*)d_in[12];
    const float* am  = (const float*)d_in[13];
    const float* avv = (const float*)d_in[14];
    const float* w1  = (const float*)d_in[15];
    const float* b1  = (const float*)d_in[16];
    const float* w2  = (const float*)d_in[17];
    const float* b2  = (const float*)d_in[18];
    const float* fg  = (const float*)d_in[19];
    const float* fb  = (const float*)d_in[20];
    const float* fm  = (const float*)d_in[21];
    const float* fv  = (const float*)d_in[22];
    float* out = (float*)d_out;

    float *px, *pbq;
    __half *pxh, *pp16, *pq16, *pk16, *pvt, *phd16, *ph16, *pwqh, *pw1h, *pw2h, *pwoh;
    cudaGetSymbolAddress((void**)&px,    g_x);
    cudaGetSymbolAddress((void**)&pxh,   g_xh);
    cudaGetSymbolAddress((void**)&pp16,  g_p16);
    cudaGetSymbolAddress((void**)&pq16,  g_q16);
    cudaGetSymbolAddress((void**)&pk16,  g_k16);
    cudaGetSymbolAddress((void**)&pvt,   g_vt);
    cudaGetSymbolAddress((void**)&phd16, g_hd16);
    cudaGetSymbolAddress((void**)&ph16,  g_h16);
    cudaGetSymbolAddress((void**)&pwqh,  g_wqh);
    cudaGetSymbolAddress((void**)&pw1h,  g_w1h);
    cudaGetSymbolAddress((void**)&pw2h,  g_w2h);
    cudaGetSymbolAddress((void**)&pwoh,  g_woh);
    cudaGetSymbolAddress((void**)&pbq,   g_bqkv);

    cudaFuncSetAttribute(hgemm<64,  TCE_QKV,  false>, cudaFuncAttributeMaxDynamicSharedMemorySize, SM64);
    cudaFuncSetAttribute(hgemm<512, TCE_SMAX, false>, cudaFuncAttributeMaxDynamicSharedMemorySize, SMS);
    cudaFuncSetAttribute(hgemm<64,  TCE_PV,   false>, cudaFuncAttributeMaxDynamicSharedMemorySize, SM64);
    cudaFuncSetAttribute(hgemm<128, TCE_RELU, false>, cudaFuncAttributeMaxDynamicSharedMemorySize, SM128);
    cudaFuncSetAttribute(hgemm<128, TCE_BN,   true >, cudaFuncAttributeMaxDynamicSharedMemorySize, SM128);
    cudaFuncSetAttribute(hgemm<128, TCE_BN,   false>, cudaFuncAttributeMaxDynamicSharedMemorySize, SM128);

    dim3 tb(32, 8);

    embed_k<<<(Mrows*Dm)/256, 256>>>(seq, emb, pes, px, pxh);                 // 0
    whalf_qkv<<<dim3(Dm/32, 2, 3), tb>>>(wq, wk, wv, pwqh);                   // 1
    biaspack<<<3, 256>>>(bqp, bkp, bvp, pbq);                                 // 2
    hgemm<64, TCE_QKV, false><<<dim3(3, 32), 512, SM64>>>(                    // 3 <- profiled
        pxh, pwqh, pbq, Dm, 1.f, nullptr, 0, pq16, pk16, pvt, 0, 0, 0,
        nullptr, nullptr, nullptr, nullptr, nullptr);

    for (int l = 1; l < NL; l++)
        whalf_qkv<<<dim3(Dm/32, 2, 3), tb>>>(wq + (size_t)l*Dm*DKh,
                                             wk + (size_t)l*Dm*DKh,
                                             wv + (size_t)l*Dm*DKh,
                                             pwqh + (size_t)l*192*Dm);
    for (int l = 0; l < NL; l++) {
        whalf<<<dim3(Dm/32, FFd/32), tb>>>(w1 + (size_t)l*Dm*FFd, Dm, FFd,
                                           pw1h + (size_t)l*FFd*Dm);
        whalf<<<dim3(FFd/32, Dm/32), tb>>>(w2 + (size_t)l*FFd*Dm, FFd, Dm,
                                           pw2h + (size_t)l*Dm*FFd);
        whalf<<<dim3(2, Dm/32), tb>>>(wo + (size_t)l*DKh*Dm, DKh, Dm,
                                      pwoh + (size_t)l*Dm*DKh);
    }

    for (int l = 0; l < NL; l++) {
        if (l > 0) {
            hgemm<64, TCE_QKV, false><<<dim3(3, 32), 512, SM64>>>(
                pxh, pwqh + (size_t)l*192*Dm, pbq + l*192, Dm, 1.f,
                nullptr, 0, pq16, pk16, pvt, 0, 0, 0,
                nullptr, nullptr, nullptr, nullptr, nullptr);
        }

        // P = softmax(Q @ K^T / 8) fused, batched over B -> fp16
        hgemm<512, TCE_SMAX, false><<<dim3(1, 4, Bq), 512, SMS>>>(
            pq16, pk16, nullptr, DKh, 0.125f, nullptr, Sq, pp16, nullptr, nullptr,
            (long)Sq*DKh, (long)Sq*DKh, (long)Sq*Sq,
            nullptr, nullptr, nullptr, nullptr, nullptr);

        // head = P @ (V^T)^T (batched) -> fp16
        hgemm<64, TCE_PV, false><<<dim3(1, 4, Bq), 512, SM64>>>(
            pp16, pvt, nullptr, Sq, 1.f, nullptr, DKh, phd16, nullptr, nullptr,
            (long)Sq*Sq, (long)DKh*Sq, (long)Sq*DKh,
            nullptr, nullptr, nullptr, nullptr, nullptr);

        // x = BN(x + head @ wo^T + bo) -> fp32 x + fp16 xh
        hgemm<128, TCE_BN, true><<<dim3(8, 32), 512, SM128>>>(
            phd16, pwoh + (size_t)l*Dm*DKh, bo + l*Dm, DKh, 1.f, px, Dm, pxh,
            nullptr, nullptr, 0, 0, 0,
            px, ag + l*Dm, ab + l*Dm, am + l*Dm, avv + l*Dm);

        // h = relu(x @ w1^T + b1) -> fp16
        hgemm<128, TCE_RELU, false><<<dim3(FFd/128, 32), 512, SM128>>>(
            pxh, pw1h + (size_t)l*FFd*Dm, b1 + l*FFd, Dm, 1.f,
            nullptr, FFd, ph16, nullptr, nullptr, 0, 0, 0,
            nullptr, nullptr, nullptr, nullptr, nullptr);

        // x = BN(x + h @ w2^T + b2)
        if (l < NL-1) {
            hgemm<128, TCE_BN, true><<<dim3(Dm/128, 32), 512, SM128>>>(
                ph16, pw2h + (size_t)l*Dm*FFd, b2 + l*Dm, FFd, 1.f, px, Dm, pxh,
                nullptr, nullptr, 0, 0, 0,
                px, fg + l*Dm, fb + l*Dm, fm + l*Dm, fv + l*Dm);
        } else {
            hgemm<128, TCE_BN, false><<<dim3(Dm/128, 32), 512, SM128>>>(
                ph16, pw2h + (size_t)l*Dm*FFd, b2 + l*Dm, FFd, 1.f, out, Dm, nullptr,
                nullptr, nullptr, 0, 0, 0,
                px, fg + l*Dm, fb + l*Dm, fm + l*Dm, fv + l*Dm);
        }
    }
}

// round 14
// speedup vs baseline: 1.0644x; 1.0644x over previous
#include <cuda_runtime.h>
#include <cuda_fp16.h>
#include <cstdint>

#define Bq 8
#define Sq 512
#define Dm 1024
#define DKh 64
#define FFd 4096
#define NL 4
#define Mrows 4096

// ---------------- scratch ----------------------------------------------------
__device__ float  g_x  [(size_t)Mrows*Dm];
__device__ __half g_xh [(size_t)Mrows*Dm];
__device__ float  g_sc [(size_t)Bq*Sq*Sq];
__device__ __half g_p16[(size_t)Bq*Sq*Sq];
__device__ __half g_q16[(size_t)Mrows*DKh];
__device__ __half g_k16[(size_t)Mrows*DKh];
__device__ __half g_vt [(size_t)Bq*DKh*Sq];
__device__ __half g_hd16[(size_t)Mrows*DKh];
__device__ __half g_h16[(size_t)Mrows*FFd];
__device__ __half g_wqh[(size_t)NL*192*Dm];
__device__ __half g_w1h[(size_t)NL*FFd*Dm];
__device__ __half g_w2h[(size_t)NL*Dm*FFd];
__device__ __half g_woh[(size_t)NL*Dm*DKh];
__device__ float  g_bqkv[NL*192];

// ---------------- helpers -----------------------------------------------------
__device__ __forceinline__ uint32_t smem_u32(const void* p){
    uint32_t a;
    asm("{ .reg .u64 t; cvta.to.shared.u64 t, %1; cvt.u32.u64 %0, t; }":"=r"(a):"l"(p));
    return a;
}
__device__ __forceinline__ void cpa16(uint32_t d, const void* s){
    asm volatile("cp.async.cg.shared.global [%0], [%1], 16;"::"r"(d),"l"(s));
}
__device__ __forceinline__ void cpa_commit(){ asm volatile("cp.async.commit_group;":::"memory"); }
__device__ __forceinline__ void cpa_wait1(){ asm volatile("cp.async.wait_group 1;":::"memory"); }
__device__ __forceinline__ void cpa_wait0(){ asm volatile("cp.async.wait_group 0;":::"memory"); }

#define LDMX4(r, addr) \
    asm volatile("ldmatrix.sync.aligned.m8n8.x4.shared.b16 {%0,%1,%2,%3}, [%4];" \
        : "=r"((r)[0]),"=r"((r)[1]),"=r"((r)[2]),"=r"((r)[3]) : "r"(addr))

#define HMMA16816(c, a, b0v, b1v) \
    asm volatile("mma.sync.aligned.m16n8k16.row.col.f32.f16.f16.f32 " \
        "{%0,%1,%2,%3}, {%4,%5,%6,%7}, {%8,%9}, {%0,%1,%2,%3};" \
        : "+f"((c)[0]),"+f"((c)[1]),"+f"((c)[2]),"+f"((c)[3]) \
        : "r"((a)[0]),"r"((a)[1]),"r"((a)[2]),"r"((a)[3]), "r"(b0v),"r"(b1v))

// ---------------- fp16 HMMA GEMM  C = epi(alpha * A @ B^T) ---------------------
// 512 threads, warp grid 4x4. A: [M,K] fp16 (batch stride sA). B: [N,K] fp16
// (stride sB). K%64==0, M%128==0, BN_%64==0.
#define TCE_QKV   0   // +bias; route fp16 to Q / K / V^T (blockIdx.x selects)
#define TCE_SCALE 1   // *alpha -> fp32 C
#define TCE_PV    2   // fp16 Oh only
#define TCE_RELU  3   // +bias, relu -> fp16 Oh
#define TCE_BN    4   // +bias+resid, BN -> fp32 C (+fp16 Oh if WB16)

template <int BN_, int EPI, bool WB16>
__global__ void __launch_bounds__(512, 1)
hgemm(const __half* __restrict__ A, const __half* __restrict__ B,
      const float* __restrict__ bias, int K, float alpha,
      float* __restrict__ Cf, int ldc,
      __half* __restrict__ Oh, __half* __restrict__ O2, __half* __restrict__ O3,
      long sA, long sB, long sC,
      const float* __restrict__ resid,
      const float* __restrict__ gamma, const float* __restrict__ beta,
      const float* __restrict__ mean,  const float* __restrict__ var)
{
    extern __shared__ __align__(1024) char smem[];
    constexpr int STG = 16384 + BN_*128;     // A(16K) + B per stage
    constexpr int WN  = BN_/4;               // warp n-width (warps 4x4)
    constexpr int NP  = WN/16;
    constexpr int NT  = WN/8;

    A += (size_t)blockIdx.z * sA;
    B += (size_t)blockIdx.z * sB;
    if (Cf) Cf += (size_t)blockIdx.z * sC;
    if (EPI == TCE_PV) Oh += (size_t)blockIdx.z * sC;

    const uint32_t sb = smem_u32(smem);
    const int tid = threadIdx.x, wid = tid>>5, lane = tid&31;
    const int m0 = blockIdx.y*128, n0 = blockIdx.x*BN_;
    const int wm = (wid>>2)*32,    wn = (wid&3)*WN;

    const int l15 = lane & 15, sg = lane >> 4;
    const int rA = wm + l15, rB = wn + l15;
    const uint32_t baseA = (uint32_t)rA * 128;
    const uint32_t baseB = (uint32_t)rB * 128;
    const uint32_t xorA  = ((uint32_t)(rA & 7)) << 4;
    const uint32_t xorB  = ((uint32_t)(rB & 7)) << 4;
    const uint32_t sgo   = ((uint32_t)sg) << 4;

    float acc[2][NT][4];
#pragma unroll
    for (int mt=0;mt<2;mt++)
#pragma unroll
        for (int nt=0;nt<NT;nt++)
#pragma unroll
            for (int q=0;q<4;q++) acc[mt][nt][q]=0.f;

    auto load_chunk = [&](int ck, int s){
        const int ko = ck << 6;
        const uint32_t aA = sb + s*STG;
        const uint32_t aB = aA + 16384;
#pragma unroll
        for (int i = 0; i < 2; i++) {
            int idx = tid + (i<<9); int r = idx>>3, seg = idx&7;
            uint32_t off = (r<<7)+(seg<<4), sw = off ^ ((off>>3)&0x70);
            size_t g = (size_t)(m0+r)*K + ko + (seg<<3);
            cpa16(aA+sw, A+g);
        }
#pragma unroll
        for (int i = 0; i < BN_/64; i++) {
            int idx = tid + (i<<9); int r = idx>>3, seg = idx&7;
            uint32_t off = (r<<7)+(seg<<4), sw = off ^ ((off>>3)&0x70);
            size_t g = (size_t)(n0+r)*K + ko + (seg<<3);
            cpa16(aB+sw, B+g);
        }
    };

    const int NC = K >> 6;
    load_chunk(0, 0);
    cpa_commit();

    for (int c = 0; c < NC; c++) {
        if (c+1 < NC) { load_chunk(c+1, (c+1)&1); cpa_commit(); cpa_wait1(); }
        else          { cpa_wait0(); }
        __syncthreads();

        const uint32_t aA = sb + (c&1)*STG;
        const uint32_t aB = aA + 16384;
#pragma unroll
        for (int ks = 0; ks < 4; ks++) {
            const uint32_t cA = (sgo | ((uint32_t)ks << 5)) ^ xorA;
            const uint32_t cB = (sgo | ((uint32_t)ks << 5)) ^ xorB;
            uint32_t af[2][4], bf[NP][4];
#pragma unroll
            for (int mt=0;mt<2;mt++) LDMX4(af[mt], aA + baseA + mt*2048 + cA);
#pragma unroll
            for (int np=0;np<NP;np++) LDMX4(bf[np], aB + baseB + np*2048 + cB);
#pragma unroll
            for (int mt=0;mt<2;mt++)
#pragma unroll
                for (int np=0;np<NP;np++) {
                    HMMA16816(acc[mt][2*np],   af[mt], bf[np][0], bf[np][2]);
                    HMMA16816(acc[mt][2*np+1], af[mt], bf[np][1], bf[np][3]);
                }
        }
        __syncthreads();
    }

    // ---- epilogue ----
    const int rb = m0 + wm + (lane>>2);
    const int cb = n0 + wn + (lane&3)*2;

    auto epi = [&](int row, int col, float v0, float v1){
        if (EPI == TCE_SCALE) {
            *(float2*)(Cf + (size_t)row*ldc + col) = make_float2(v0*alpha, v1*alpha);
            return;
        }
        if (EPI == TCE_PV) {
            *(__half2*)(Oh + (size_t)row*ldc + col) =
                __halves2half2(__float2half_rn(v0), __float2half_rn(v1));
            return;
        }
        v0 += bias[col]; v1 += bias[col+1];
        if (EPI == TCE_QKV) {
            __half h0 = __float2half_rn(v0), h1 = __float2half_rn(v1);
            if (blockIdx.x < 2) {
                __half* dst = (blockIdx.x == 0) ? Oh : O2;
                *(__half2*)(dst + (size_t)row*DKh + (col & 63)) = __halves2half2(h0, h1);
            } else {
                int b = row >> 9, mi = row & 511;
                O3[((size_t)b*DKh + (col-128))*Sq + mi] = h0;
                O3[((size_t)b*DKh + (col-127))*Sq + mi] = h1;
            }
            return;
        }
        if (EPI == TCE_RELU) { v0 = fmaxf(v0, 0.f); v1 = fmaxf(v1, 0.f); }
        if (EPI == TCE_BN) {
            float2 rs = *(const float2*)(resid + (size_t)row*ldc + col);
            v0 += rs.x; v1 += rs.y;
            v0 = gamma[col]  *(v0 - mean[col])  *rsqrtf(var[col]  +1e-3f) + beta[col];
            v1 = gamma[col+1]*(v1 - mean[col+1])*rsqrtf(var[col+1]+1e-3f) + beta[col+1];
        }
        if (EPI != TCE_RELU)
            *(float2*)(Cf + (size_t)row*ldc + col) = make_float2(v0, v1);
        if (WB16 || EPI == TCE_RELU)
            *(__half2*)(Oh + (size_t)row*ldc + col) =
                __halves2half2(__float2half_rn(v0), __float2half_rn(v1));
    };

#pragma unroll
    for (int mt=0;mt<2;mt++)
#pragma unroll
        for (int nt=0;nt<NT;nt++) {
            const int col = cb + nt*8;
            epi(rb + mt*16,     col, acc[mt][nt][0], acc[mt][nt][1]);
            epi(rb + mt*16 + 8, col, acc[mt][nt][2], acc[mt][nt][3]);
        }
}

// ------ vectorized transpose to fp16: in[K,N] -> out[N,K], batched over z ------
__global__ void whalfT(const float* __restrict__ in, int K, int N,
                       long inS, __half* __restrict__ out, long outS)
{
    __shared__ float t[64][33];
    in  += (size_t)blockIdx.z * inS;
    out += (size_t)blockIdx.z * outS;
    const int k0 = blockIdx.x*64, n0 = blockIdx.y*32;
    const int tx = threadIdx.x, ty = threadIdx.y;
#pragma unroll
    for (int r = ty; r < 64; r += 8)
        t[r][tx] = in[(size_t)(k0+r)*N + n0 + tx];
    __syncthreads();
#pragma unroll
    for (int j = ty; j < 32; j += 8) {
        __half2 v = __halves2half2(__float2half_rn(t[2*tx][j]),
                                   __float2half_rn(t[2*tx+1][j]));
        *(__half2*)(out + (size_t)(n0+j)*K + k0 + 2*tx) = v;
    }
}

// QKV weights: [Dm, DKh] x 3 matrices x NL layers -> packed [192, Dm] per layer
__global__ void whalfT_qkv(const float* __restrict__ wq, const float* __restrict__ wk,
                           const float* __restrict__ wv, __half* __restrict__ out)
{
    __shared__ float t[64][33];
    const int mat = blockIdx.y >> 1;
    const int l = blockIdx.z;
    const float* in = ((mat == 0) ? wq : (mat == 1) ? wk : wv) + (size_t)l*Dm*DKh;
    __half* o = out + (size_t)l*192*Dm + (size_t)mat*DKh*Dm;
    const int k0 = blockIdx.x*64, n0 = (blockIdx.y & 1)*32;
    const int tx = threadIdx.x, ty = threadIdx.y;
#pragma unroll
    for (int r = ty; r < 64; r += 8)
        t[r][tx] = in[(size_t)(k0+r)*DKh + n0 + tx];
    __syncthreads();
#pragma unroll
    for (int j = ty; j < 32; j += 8) {
        __half2 v = __halves2half2(__float2half_rn(t[2*tx][j]),
                                   __float2half_rn(t[2*tx+1][j]));
        *(__half2*)(o + (size_t)(n0+j)*Dm + k0 + 2*tx) = v;
    }
}

__global__ void biaspack(const float* bq, const float* bk, const float* bv, float* o)
{
    int t = threadIdx.x + blockIdx.x*256;
    if (t >= NL*192) return;
    int l = t/192, j = t%192;
    o[t] = (j < 64) ? bq[l*64+j] : (j < 128) ? bk[l*64+j-64] : bv[l*64+j-128];
}

// ---------------- embed + fp16 ------------------------------------------------
__global__ void embed_k(const int* __restrict__ seq, const float* __restrict__ emb,
                        const float* __restrict__ pes, float* __restrict__ x,
                        __half* __restrict__ xh)
{
    size_t idx = (size_t)blockIdx.x*256 + threadIdx.x;
    int d = (int)(idx & (Dm-1));
    size_t bs = idx >> 10;
    int s = (int)(bs & (Sq-1));
    float v = emb[(size_t)seq[bs]*Dm + d] + pes[(size_t)s*Dm];
    x[idx] = v;
    xh[idx] = __float2half_rn(v);
}

// ---------------- softmax: fp32 in -> fp16 probabilities -----------------------
__global__ void softmax_k(const float* __restrict__ S, __half* __restrict__ P)
{
    const float* p = S + (size_t)blockIdx.x*Sq;
    __half* o = P + (size_t)blockIdx.x*Sq;
    const int t = threadIdx.x;
    __shared__ float red[256];
    float v0 = p[t], v1 = p[t+256];
    red[t] = fmaxf(v0, v1); __syncthreads();
    for (int ofs = 128; ofs > 0; ofs >>= 1) { if (t < ofs) red[t] = fmaxf(red[t], red[t+ofs]); __syncthreads(); }
    const float m = red[0]; __syncthreads();
    float e0 = __expf(v0-m), e1 = __expf(v1-m);
    red[t] = e0 + e1; __syncthreads();
    for (int ofs = 128; ofs > 0; ofs >>= 1) { if (t < ofs) red[t] += red[t+ofs]; __syncthreads(); }
    const float inv = 1.f/red[0];
    o[t]     = __float2half_rn(e0*inv);
    o[t+256] = __float2half_rn(e1*inv);
}

// ---------------- host ----------------------------------------------------------
static const int SM64  = 2*(16384 + 64*128);     // 49152
static const int SM128 = 2*(16384 + 128*128);    // 65536

extern "C" void kernel_launch(void* const* d_in, const int* in_sizes, int n_in,
                              void* d_out, int out_size)
{
    const int*   seq = (const int*)  d_in[0];
    const float* emb = (const float*)d_in[1];
    const float* pes = (const float*)d_in[2];
    const float* wq  = (const float*)d_in[3];
    const float* bqp = (const float*)d_in[4];
    const float* wk  = (const float*)d_in[5];
    const float* bkp = (const float*)d_in[6];
    const float* wv  = (const float*)d_in[7];
    const float* bvp = (const float*)d_in[8];
    const float* wo  = (const float*)d_in[9];
    const float* bo  = (const float*)d_in[10];
    const float* ag  = (const float*)d_in[11];
    const float* ab  = (const float*)d_in[12];
    const float* am  = (const float*)d_in[13];
    const float* avv = (const float*)d_in[14];
    const float* w1  = (const float*)d_in[15];
    const float* b1  = (const float*)d_in[16];
    const float* w2  = (const float*)d_in[17];
    const float* b2  = (const float*)d_in[18];
    const float* fg  = (const float*)d_in[19];
    const float* fb  = (const float*)d_in[20];
    const float* fm  = (const float*)d_in[21];
    const float* fv  = (const float*)d_in[22];
    float* out = (float*)d_out;

    float *px, *psc, *pbq;
    __half *pxh, *pp16, *pq16, *pk16, *pvt, *phd16, *ph16, *pwqh, *pw1h, *pw2h, *pwoh;
    cudaGetSymbolAddress((void**)&px,    g_x);
    cudaGetSymbolAddress((void**)&pxh,   g_xh);
    cudaGetSymbolAddress((void**)&psc,   g_sc);
    cudaGetSymbolAddress((void**)&pp16,  g_p16);
    cudaGetSymbolAddress((void**)&pq16,  g_q16);
    cudaGetSymbolAddress((void**)&pk16,  g_k16);
    cudaGetSymbolAddress((void**)&pvt,   g_vt);
    cudaGetSymbolAddress((void**)&phd16, g_hd16);
    cudaGetSymbolAddress((void**)&ph16,  g_h16);
    cudaGetSymbolAddress((void**)&pwqh,  g_wqh);
    cudaGetSymbolAddress((void**)&pw1h,  g_w1h);
    cudaGetSymbolAddress((void**)&pw2h,  g_w2h);
    cudaGetSymbolAddress((void**)&pwoh,  g_woh);
    cudaGetSymbolAddress((void**)&pbq,   g_bqkv);

    cudaFuncSetAttribute(hgemm<64,  TCE_QKV,   false>, cudaFuncAttributeMaxDynamicSharedMemorySize, SM64);
    cudaFuncSetAttribute(hgemm<128, TCE_SCALE, false>, cudaFuncAttributeMaxDynamicSharedMemorySize, SM128);
    cudaFuncSetAttribute(hgemm<64,  TCE_PV,    false>, cudaFuncAttributeMaxDynamicSharedMemorySize, SM64);
    cudaFuncSetAttribute(hgemm<128, TCE_RELU,  false>, cudaFuncAttributeMaxDynamicSharedMemorySize, SM128);
    cudaFuncSetAttribute(hgemm<128, TCE_BN,    true >, cudaFuncAttributeMaxDynamicSharedMemorySize, SM128);
    cudaFuncSetAttribute(hgemm<128, TCE_BN,    false>, cudaFuncAttributeMaxDynamicSharedMemorySize, SM128);

    // one-time side-stream + events (created outside capture on first call)
    static cudaStream_t s2 = nullptr;
    static cudaEvent_t evF = nullptr, evJ = nullptr;
    if (!s2) {
        cudaStreamCreateWithFlags(&s2, cudaStreamNonBlocking);
        cudaEventCreateWithFlags(&evF, cudaEventDisableTiming);
        cudaEventCreateWithFlags(&evJ, cudaEventDisableTiming);
    }

    dim3 tb(32, 8);

    // main stream: embed + QKV weight prep (all layers) + bias pack
    embed_k<<<(Mrows*Dm)/256, 256>>>(seq, emb, pes, px, pxh);
    whalfT_qkv<<<dim3(Dm/64, 6, NL), tb>>>(wq, wk, wv, pwqh);
    biaspack<<<3, 256>>>(bqp, bkp, bvp, pbq);

    // fork: wo/w1/w2 prep on s2, overlapping layer-0 attention
    cudaEventRecord(evF, 0);
    cudaStreamWaitEvent(s2, evF, 0);
    whalfT<<<dim3(1, Dm/32, NL), tb, 0, s2>>>(wo, DKh, Dm, (long)DKh*Dm, pwoh, (long)Dm*DKh);
    whalfT<<<dim3(Dm/64, FFd/32, NL), tb, 0, s2>>>(w1, Dm, FFd, (long)Dm*FFd, pw1h, (long)FFd*Dm);
    whalfT<<<dim3(FFd/64, Dm/32, NL), tb, 0, s2>>>(w2, FFd, Dm, (long)FFd*Dm, pw2h, (long)Dm*FFd);
    cudaEventRecord(evJ, s2);

    bool joined = false;
    for (int l = 0; l < NL; l++) {
        // QKV fused: writes fp16 Q, K, V^T
        hgemm<64, TCE_QKV, false><<<dim3(3, 32), 512, SM64>>>(
            pxh, pwqh + (size_t)l*192*Dm, pbq + l*192, Dm, 1.f,
            nullptr, 0, pq16, pk16, pvt, 0, 0, 0,
            nullptr, nullptr, nullptr, nullptr, nullptr);

        // scores = Q @ K^T / 8 (batched) -> fp32
        hgemm<128, TCE_SCALE, false><<<dim3(4, 4, Bq), 512, SM128>>>(
            pq16, pk16, nullptr, DKh, 0.125f, psc, Sq, nullptr, nullptr, nullptr,
            (long)Sq*DKh, (long)Sq*DKh, (long)Sq*Sq,
            nullptr, nullptr, nullptr, nullptr, nullptr);

        softmax_k<<<Mrows, 256>>>(psc, pp16);

        // head = P @ (V^T)^T (batched) -> fp16
        hgemm<64, TCE_PV, false><<<dim3(1, 4, Bq), 512, SM64>>>(
            pp16, pvt, nullptr, Sq, 1.f, nullptr, DKh, phd16, nullptr, nullptr,
            (long)Sq*Sq, (long)DKh*Sq, (long)Sq*DKh,
            nullptr, nullptr, nullptr, nullptr, nullptr);

        if (!joined) { cudaStreamWaitEvent(0, evJ, 0); joined = true; }

        // x = BN(x + head @ wo^T + bo) -> fp32 x + fp16 xh
        hgemm<128, TCE_BN, true><<<dim3(8, 32), 512, SM128>>>(
            phd16, pwoh + (size_t)l*Dm*DKh, bo + l*Dm, DKh, 1.f, px, Dm, pxh,
            nullptr, nullptr, 0, 0, 0,
            px, ag + l*Dm, ab + l*Dm, am + l*Dm, avv + l*Dm);

        // h = relu(x @ w1^T + b1) -> fp16
        hgemm<128, TCE_RELU, false><<<dim3(FFd/128, 32), 512, SM128>>>(
            pxh, pw1h + (size_t)l*FFd*Dm, b1 + l*FFd, Dm, 1.f,
            nullptr, FFd, ph16, nullptr, nullptr, 0, 0, 0,
            nullptr, nullptr, nullptr, nullptr, nullptr);

        // x = BN(x + h @ w2^T + b2)
        if (l < NL-1) {
            hgemm<128, TCE_BN, true><<<dim3(Dm/128, 32), 512, SM128>>>(
                ph16, pw2h + (size_t)l*Dm*FFd, b2 + l*Dm, FFd, 1.f, px, Dm, pxh,
                nullptr, nullptr, 0, 0, 0,
                px, fg + l*Dm, fb + l*Dm, fm + l*Dm, fv + l*Dm);
        } else {
            hgemm<128, TCE_BN, false><<<dim3(Dm/128, 32), 512, SM128>>>(
                ph16, pw2h + (size_t)l*Dm*FFd, b2 + l*Dm, FFd, 1.f, out, Dm, nullptr,
                nullptr, nullptr, 0, 0, 0,
                px, fg + l*Dm, fb + l*Dm, fm + l*Dm, fv + l*Dm);
        }
    }
}

// round 15
// speedup vs baseline: 1.0846x; 1.0190x over previous
#include <cuda_runtime.h>
#include <cuda_fp16.h>
#include <cstdint>

#define Bq 8
#define Sq 512
#define Dm 1024
#define DKh 64
#define FFd 4096
#define NL 4
#define Mrows 4096

// ---------------- scratch ----------------------------------------------------
__device__ float  g_x  [(size_t)Mrows*Dm];
__device__ __half g_xh [(size_t)Mrows*Dm];
__device__ float  g_sc [(size_t)Bq*Sq*Sq];
__device__ __half g_p16[(size_t)Bq*Sq*Sq];
__device__ __half g_q16[(size_t)Mrows*DKh];
__device__ __half g_k16[(size_t)Mrows*DKh];
__device__ __half g_vt [(size_t)Bq*DKh*Sq];
__device__ __half g_hd16[(size_t)Mrows*DKh];
__device__ __half g_h16[(size_t)Mrows*FFd];
__device__ __half g_wqh[(size_t)NL*192*Dm];
__device__ __half g_w1h[(size_t)NL*FFd*Dm];
__device__ __half g_w2h[(size_t)NL*Dm*FFd];
__device__ __half g_woh[(size_t)NL*Dm*DKh];
__device__ float  g_bqkv[NL*192];

// ---------------- helpers -----------------------------------------------------
__device__ __forceinline__ uint32_t smem_u32(const void* p){
    uint32_t a;
    asm("{ .reg .u64 t; cvta.to.shared.u64 t, %1; cvt.u32.u64 %0, t; }":"=r"(a):"l"(p));
    return a;
}
__device__ __forceinline__ void cpa16(uint32_t d, const void* s){
    asm volatile("cp.async.cg.shared.global [%0], [%1], 16;"::"r"(d),"l"(s));
}
__device__ __forceinline__ void cpa_commit(){ asm volatile("cp.async.commit_group;":::"memory"); }
__device__ __forceinline__ void cpa_wait1(){ asm volatile("cp.async.wait_group 1;":::"memory"); }
__device__ __forceinline__ void cpa_wait0(){ asm volatile("cp.async.wait_group 0;":::"memory"); }

#define LDMX4(r, addr) \
    asm volatile("ldmatrix.sync.aligned.m8n8.x4.shared.b16 {%0,%1,%2,%3}, [%4];" \
        : "=r"((r)[0]),"=r"((r)[1]),"=r"((r)[2]),"=r"((r)[3]) : "r"(addr))

#define HMMA16816(c, a, b0v, b1v) \
    asm volatile("mma.sync.aligned.m16n8k16.row.col.f32.f16.f16.f32 " \
        "{%0,%1,%2,%3}, {%4,%5,%6,%7}, {%8,%9}, {%0,%1,%2,%3};" \
        : "+f"((c)[0]),"+f"((c)[1]),"+f"((c)[2]),"+f"((c)[3]) \
        : "r"((a)[0]),"r"((a)[1]),"r"((a)[2]),"r"((a)[3]), "r"(b0v),"r"(b1v))

// ---------------- fp16 HMMA GEMM  C = epi(alpha * A @ B^T) ---------------------
// 512 threads, warp grid 4x4. A: [M,K] fp16 (batch stride sA). B: [N,K] fp16
// (stride sB). K%64==0, M%128==0, BN_%64==0.
#define TCE_QKV   0   // +bias; route fp16 to Q / K / V^T (blockIdx.x selects)
#define TCE_SCALE 1   // *alpha -> fp32 C
#define TCE_PV    2   // fp16 Oh only
#define TCE_RELU  3   // +bias, relu -> fp16 Oh
#define TCE_BN    4   // +bias+resid, BN -> fp32 C (+fp16 Oh if WB16)

template <int BN_, int EPI, bool WB16>
__global__ void __launch_bounds__(512, 1)
hgemm(const __half* __restrict__ A, const __half* __restrict__ B,
      const float* __restrict__ bias, int K, float alpha,
      float* __restrict__ Cf, int ldc,
      __half* __restrict__ Oh, __half* __restrict__ O2, __half* __restrict__ O3,
      long sA, long sB, long sC,
      const float* __restrict__ resid,
      const float* __restrict__ gamma, const float* __restrict__ beta,
      const float* __restrict__ mean,  const float* __restrict__ var)
{
    extern __shared__ __align__(1024) char smem[];
    constexpr int STG = 16384 + BN_*128;
    constexpr int WN  = BN_/4;
    constexpr int NP  = WN/16;
    constexpr int NT  = WN/8;

    A += (size_t)blockIdx.z * sA;
    B += (size_t)blockIdx.z * sB;
    if (Cf) Cf += (size_t)blockIdx.z * sC;
    if (EPI == TCE_PV) Oh += (size_t)blockIdx.z * sC;

    const uint32_t sb = smem_u32(smem);
    const int tid = threadIdx.x, wid = tid>>5, lane = tid&31;
    const int m0 = blockIdx.y*128, n0 = blockIdx.x*BN_;
    const int wm = (wid>>2)*32,    wn = (wid&3)*WN;

    const int l15 = lane & 15, sg = lane >> 4;
    const int rA = wm + l15, rB = wn + l15;
    const uint32_t baseA = (uint32_t)rA * 128;
    const uint32_t baseB = (uint32_t)rB * 128;
    const uint32_t xorA  = ((uint32_t)(rA & 7)) << 4;
    const uint32_t xorB  = ((uint32_t)(rB & 7)) << 4;
    const uint32_t sgo   = ((uint32_t)sg) << 4;

    float acc[2][NT][4];
#pragma unroll
    for (int mt=0;mt<2;mt++)
#pragma unroll
        for (int nt=0;nt<NT;nt++)
#pragma unroll
            for (int q=0;q<4;q++) acc[mt][nt][q]=0.f;

    auto load_chunk = [&](int ck, int s){
        const int ko = ck << 6;
        const uint32_t aA = sb + s*STG;
        const uint32_t aB = aA + 16384;
#pragma unroll
        for (int i = 0; i < 2; i++) {
            int idx = tid + (i<<9); int r = idx>>3, seg = idx&7;
            uint32_t off = (r<<7)+(seg<<4), sw = off ^ ((off>>3)&0x70);
            size_t g = (size_t)(m0+r)*K + ko + (seg<<3);
            cpa16(aA+sw, A+g);
        }
#pragma unroll
        for (int i = 0; i < BN_/64; i++) {
            int idx = tid + (i<<9); int r = idx>>3, seg = idx&7;
            uint32_t off = (r<<7)+(seg<<4), sw = off ^ ((off>>3)&0x70);
            size_t g = (size_t)(n0+r)*K + ko + (seg<<3);
            cpa16(aB+sw, B+g);
        }
    };

    const int NC = K >> 6;
    load_chunk(0, 0);
    cpa_commit();

    for (int c = 0; c < NC; c++) {
        if (c+1 < NC) { load_chunk(c+1, (c+1)&1); cpa_commit(); cpa_wait1(); }
        else          { cpa_wait0(); }
        __syncthreads();

        const uint32_t aA = sb + (c&1)*STG;
        const uint32_t aB = aA + 16384;
#pragma unroll
        for (int ks = 0; ks < 4; ks++) {
            const uint32_t cA = (sgo | ((uint32_t)ks << 5)) ^ xorA;
            const uint32_t cB = (sgo | ((uint32_t)ks << 5)) ^ xorB;
            uint32_t af[2][4], bf[NP][4];
#pragma unroll
            for (int mt=0;mt<2;mt++) LDMX4(af[mt], aA + baseA + mt*2048 + cA);
#pragma unroll
            for (int np=0;np<NP;np++) LDMX4(bf[np], aB + baseB + np*2048 + cB);
#pragma unroll
            for (int mt=0;mt<2;mt++)
#pragma unroll
                for (int np=0;np<NP;np++) {
                    HMMA16816(acc[mt][2*np],   af[mt], bf[np][0], bf[np][2]);
                    HMMA16816(acc[mt][2*np+1], af[mt], bf[np][1], bf[np][3]);
                }
        }
        __syncthreads();
    }

    // ---- epilogue ----
    const int rb = m0 + wm + (lane>>2);
    const int cb = n0 + wn + (lane&3)*2;

    auto epi = [&](int row, int col, float v0, float v1){
        if (EPI == TCE_SCALE) {
            *(float2*)(Cf + (size_t)row*ldc + col) = make_float2(v0*alpha, v1*alpha);
            return;
        }
        if (EPI == TCE_PV) {
            *(__half2*)(Oh + (size_t)row*ldc + col) =
                __halves2half2(__float2half_rn(v0), __float2half_rn(v1));
            return;
        }
        v0 += bias[col]; v1 += bias[col+1];
        if (EPI == TCE_QKV) {
            __half h0 = __float2half_rn(v0), h1 = __float2half_rn(v1);
            if (blockIdx.x < 2) {
                __half* dst = (blockIdx.x == 0) ? Oh : O2;
                *(__half2*)(dst + (size_t)row*DKh + (col & 63)) = __halves2half2(h0, h1);
            } else {
                int b = row >> 9, mi = row & 511;
                O3[((size_t)b*DKh + (col-128))*Sq + mi] = h0;
                O3[((size_t)b*DKh + (col-127))*Sq + mi] = h1;
            }
            return;
        }
        if (EPI == TCE_RELU) { v0 = fmaxf(v0, 0.f); v1 = fmaxf(v1, 0.f); }
        if (EPI == TCE_BN) {
            float2 rs = *(const float2*)(resid + (size_t)row*ldc + col);
            v0 += rs.x; v1 += rs.y;
            v0 = gamma[col]  *(v0 - mean[col])  *rsqrtf(var[col]  +1e-3f) + beta[col];
            v1 = gamma[col+1]*(v1 - mean[col+1])*rsqrtf(var[col+1]+1e-3f) + beta[col+1];
        }
        if (EPI != TCE_RELU)
            *(float2*)(Cf + (size_t)row*ldc + col) = make_float2(v0, v1);
        if (WB16 || EPI == TCE_RELU)
            *(__half2*)(Oh + (size_t)row*ldc + col) =
                __halves2half2(__float2half_rn(v0), __float2half_rn(v1));
    };

#pragma unroll
    for (int mt=0;mt<2;mt++)
#pragma unroll
        for (int nt=0;nt<NT;nt++) {
            const int col = cb + nt*8;
            epi(rb + mt*16,     col, acc[mt][nt][0], acc[mt][nt][1]);
            epi(rb + mt*16 + 8, col, acc[mt][nt][2], acc[mt][nt][3]);
        }
}

// ------ vectorized transpose to fp16: in[K,N] -> out[N,K], batched over z ------
__global__ void whalfT(const float* __restrict__ in, int K, int N,
                       long inS, __half* __restrict__ out, long outS)
{
    __shared__ float t[64][33];
    in  += (size_t)blockIdx.z * inS;
    out += (size_t)blockIdx.z * outS;
    const int k0 = blockIdx.x*64, n0 = blockIdx.y*32;
    const int tx = threadIdx.x, ty = threadIdx.y;
#pragma unroll
    for (int r = ty; r < 64; r += 8)
        t[r][tx] = in[(size_t)(k0+r)*N + n0 + tx];
    __syncthreads();
#pragma unroll
    for (int j = ty; j < 32; j += 8) {
        __half2 v = __halves2half2(__float2half_rn(t[2*tx][j]),
                                   __float2half_rn(t[2*tx+1][j]));
        *(__half2*)(out + (size_t)(n0+j)*K + k0 + 2*tx) = v;
    }
}

// QKV weights: [Dm, DKh] x 3 matrices x NL layers -> packed [192, Dm] per layer
__global__ void whalfT_qkv(const float* __restrict__ wq, const float* __restrict__ wk,
                           const float* __restrict__ wv, __half* __restrict__ out)
{
    __shared__ float t[64][33];
    const int mat = blockIdx.y >> 1;
    const int l = blockIdx.z;
    const float* in = ((mat == 0) ? wq : (mat == 1) ? wk : wv) + (size_t)l*Dm*DKh;
    __half* o = out + (size_t)l*192*Dm + (size_t)mat*DKh*Dm;
    const int k0 = blockIdx.x*64, n0 = (blockIdx.y & 1)*32;
    const int tx = threadIdx.x, ty = threadIdx.y;
#pragma unroll
    for (int r = ty; r < 64; r += 8)
        t[r][tx] = in[(size_t)(k0+r)*DKh + n0 + tx];
    __syncthreads();
#pragma unroll
    for (int j = ty; j < 32; j += 8) {
        __half2 v = __halves2half2(__float2half_rn(t[2*tx][j]),
                                   __float2half_rn(t[2*tx+1][j]));
        *(__half2*)(o + (size_t)(n0+j)*Dm + k0 + 2*tx) = v;
    }
}

__global__ void biaspack(const float* bq, const float* bk, const float* bv, float* o)
{
    int t = threadIdx.x + blockIdx.x*256;
    if (t >= NL*192) return;
    int l = t/192, j = t%192;
    o[t] = (j < 64) ? bq[l*64+j] : (j < 128) ? bk[l*64+j-64] : bv[l*64+j-128];
}

// ---------------- embed + fp16 ------------------------------------------------
__global__ void embed_k(const int* __restrict__ seq, const float* __restrict__ emb,
                        const float* __restrict__ pes, float* __restrict__ x,
                        __half* __restrict__ xh)
{
    size_t idx = (size_t)blockIdx.x*256 + threadIdx.x;
    int d = (int)(idx & (Dm-1));
    size_t bs = idx >> 10;
    int s = (int)(bs & (Sq-1));
    float v = emb[(size_t)seq[bs]*Dm + d] + pes[(size_t)s*Dm];
    x[idx] = v;
    xh[idx] = __float2half_rn(v);
}

// -------- softmax: one warp per 512-col row, shfl-only, fp32 -> fp16 -----------
__global__ void softmax_w(const float* __restrict__ S, __half* __restrict__ P)
{
    const int row  = blockIdx.x*8 + (threadIdx.x >> 5);
    const int lane = threadIdx.x & 31;
    const float* p = S + (size_t)row*Sq;
    __half* o = P + (size_t)row*Sq;

    float4 v[4];
#pragma unroll
    for (int i = 0; i < 4; i++)
        v[i] = *(const float4*)(p + i*128 + lane*4);

    float mx = -1e30f;
#pragma unroll
    for (int i = 0; i < 4; i++)
        mx = fmaxf(mx, fmaxf(fmaxf(v[i].x, v[i].y), fmaxf(v[i].z, v[i].w)));
#pragma unroll
    for (int ofs = 16; ofs > 0; ofs >>= 1)
        mx = fmaxf(mx, __shfl_xor_sync(0xffffffffu, mx, ofs));

    float sum = 0.f;
#pragma unroll
    for (int i = 0; i < 4; i++) {
        v[i].x = __expf(v[i].x - mx); v[i].y = __expf(v[i].y - mx);
        v[i].z = __expf(v[i].z - mx); v[i].w = __expf(v[i].w - mx);
        sum += v[i].x + v[i].y + v[i].z + v[i].w;
    }
#pragma unroll
    for (int ofs = 16; ofs > 0; ofs >>= 1)
        sum += __shfl_xor_sync(0xffffffffu, sum, ofs);
    const float inv = 1.f / sum;

#pragma unroll
    for (int i = 0; i < 4; i++) {
        __half2 h0 = __halves2half2(__float2half_rn(v[i].x*inv), __float2half_rn(v[i].y*inv));
        __half2 h1 = __halves2half2(__float2half_rn(v[i].z*inv), __float2half_rn(v[i].w*inv));
        *(__half2*)(o + i*128 + lane*4)     = h0;
        *(__half2*)(o + i*128 + lane*4 + 2) = h1;
    }
}

// ---------------- host ----------------------------------------------------------
static const int SM64  = 2*(16384 + 64*128);     // 49152
static const int SM128 = 2*(16384 + 128*128);    // 65536

extern "C" void kernel_launch(void* const* d_in, const int* in_sizes, int n_in,
                              void* d_out, int out_size)
{
    const int*   seq = (const int*)  d_in[0];
    const float* emb = (const float*)d_in[1];
    const float* pes = (const float*)d_in[2];
    const float* wq  = (const float*)d_in[3];
    const float* bqp = (const float*)d_in[4];
    const float* wk  = (const float*)d_in[5];
    const float* bkp = (const float*)d_in[6];
    const float* wv  = (const float*)d_in[7];
    const float* bvp = (const float*)d_in[8];
    const float* wo  = (const float*)d_in[9];
    const float* bo  = (const float*)d_in[10];
    const float* ag  = (const float*)d_in[11];
    const float* ab  = (const float*)d_in[12];
    const float* am  = (const float*)d_in[13];
    const float* avv = (const float*)d_in[14];
    const float* w1  = (const float*)d_in[15];
    const float* b1  = (const float*)d_in[16];
    const float* w2  = (const float*)d_in[17];
    const float* b2  = (const float*)d_in[18];
    const float* fg  = (const float*)d_in[19];
    const float* fb  = (const float*)d_in[20];
    const float* fm  = (const float*)d_in[21];
    const float* fv  = (const float*)d_in[22];
    float* out = (float*)d_out;

    float *px, *psc, *pbq;
    __half *pxh, *pp16, *pq16, *pk16, *pvt, *phd16, *ph16, *pwqh, *pw1h, *pw2h, *pwoh;
    cudaGetSymbolAddress((void**)&px,    g_x);
    cudaGetSymbolAddress((void**)&pxh,   g_xh);
    cudaGetSymbolAddress((void**)&psc,   g_sc);
    cudaGetSymbolAddress((void**)&pp16,  g_p16);
    cudaGetSymbolAddress((void**)&pq16,  g_q16);
    cudaGetSymbolAddress((void**)&pk16,  g_k16);
    cudaGetSymbolAddress((void**)&pvt,   g_vt);
    cudaGetSymbolAddress((void**)&phd16, g_hd16);
    cudaGetSymbolAddress((void**)&ph16,  g_h16);
    cudaGetSymbolAddress((void**)&pwqh,  g_wqh);
    cudaGetSymbolAddress((void**)&pw1h,  g_w1h);
    cudaGetSymbolAddress((void**)&pw2h,  g_w2h);
    cudaGetSymbolAddress((void**)&pwoh,  g_woh);
    cudaGetSymbolAddress((void**)&pbq,   g_bqkv);

    cudaFuncSetAttribute(hgemm<64,  TCE_QKV,   false>, cudaFuncAttributeMaxDynamicSharedMemorySize, SM64);
    cudaFuncSetAttribute(hgemm<128, TCE_SCALE, false>, cudaFuncAttributeMaxDynamicSharedMemorySize, SM128);
    cudaFuncSetAttribute(hgemm<64,  TCE_PV,    false>, cudaFuncAttributeMaxDynamicSharedMemorySize, SM64);
    cudaFuncSetAttribute(hgemm<128, TCE_RELU,  false>, cudaFuncAttributeMaxDynamicSharedMemorySize, SM128);
    cudaFuncSetAttribute(hgemm<128, TCE_BN,    true >, cudaFuncAttributeMaxDynamicSharedMemorySize, SM128);
    cudaFuncSetAttribute(hgemm<128, TCE_BN,    false>, cudaFuncAttributeMaxDynamicSharedMemorySize, SM128);

    static cudaStream_t s2 = nullptr;
    static cudaEvent_t evF = nullptr, evQ = nullptr, evJ = nullptr;
    if (!s2) {
        cudaStreamCreateWithFlags(&s2, cudaStreamNonBlocking);
        cudaEventCreateWithFlags(&evF, cudaEventDisableTiming);
        cudaEventCreateWithFlags(&evQ, cudaEventDisableTiming);
        cudaEventCreateWithFlags(&evJ, cudaEventDisableTiming);
    }

    dim3 tb(32, 8);

    // fork immediately: ALL weight prep runs on s2, overlapping embed + layer-0
    cudaEventRecord(evF, 0);
    cudaStreamWaitEvent(s2, evF, 0);
    whalfT_qkv<<<dim3(Dm/64, 6, NL), tb, 0, s2>>>(wq, wk, wv, pwqh);
    biaspack<<<3, 256, 0, s2>>>(bqp, bkp, bvp, pbq);
    cudaEventRecord(evQ, s2);
    whalfT<<<dim3(1, Dm/32, NL), tb, 0, s2>>>(wo, DKh, Dm, (long)DKh*Dm, pwoh, (long)Dm*DKh);
    whalfT<<<dim3(Dm/64, FFd/32, NL), tb, 0, s2>>>(w1, Dm, FFd, (long)Dm*FFd, pw1h, (long)FFd*Dm);
    whalfT<<<dim3(FFd/64, Dm/32, NL), tb, 0, s2>>>(w2, FFd, Dm, (long)FFd*Dm, pw2h, (long)Dm*FFd);
    cudaEventRecord(evJ, s2);

    // main: embed, then wait for QKV weights
    embed_k<<<(Mrows*Dm)/256, 256>>>(seq, emb, pes, px, pxh);
    cudaStreamWaitEvent(0, evQ, 0);

    bool joined = false;
    for (int l = 0; l < NL; l++) {
        // QKV fused: writes fp16 Q, K, V^T
        hgemm<64, TCE_QKV, false><<<dim3(3, 32), 512, SM64>>>(
            pxh, pwqh + (size_t)l*192*Dm, pbq + l*192, Dm, 1.f,
            nullptr, 0, pq16, pk16, pvt, 0, 0, 0,
            nullptr, nullptr, nullptr, nullptr, nullptr);

        // scores = Q @ K^T / 8 (batched) -> fp32
        hgemm<128, TCE_SCALE, false><<<dim3(4, 4, Bq), 512, SM128>>>(
            pq16, pk16, nullptr, DKh, 0.125f, psc, Sq, nullptr, nullptr, nullptr,
            (long)Sq*DKh, (long)Sq*DKh, (long)Sq*Sq,
            nullptr, nullptr, nullptr, nullptr, nullptr);

        softmax_w<<<Mrows/8, 256>>>(psc, pp16);

        // head = P @ (V^T)^T (batched) -> fp16
        hgemm<64, TCE_PV, false><<<dim3(1, 4, Bq), 512, SM64>>>(
            pp16, pvt, nullptr, Sq, 1.f, nullptr, DKh, phd16, nullptr, nullptr,
            (long)Sq*Sq, (long)DKh*Sq, (long)Sq*DKh,
            nullptr, nullptr, nullptr, nullptr, nullptr);

        if (!joined) { cudaStreamWaitEvent(0, evJ, 0); joined = true; }

        // x = BN(x + head @ wo^T + bo) -> fp32 x + fp16 xh
        hgemm<128, TCE_BN, true><<<dim3(8, 32), 512, SM128>>>(
            phd16, pwoh + (size_t)l*Dm*DKh, bo + l*Dm, DKh, 1.f, px, Dm, pxh,
            nullptr, nullptr, 0, 0, 0,
            px, ag + l*Dm, ab + l*Dm, am + l*Dm, avv + l*Dm);

        // h = relu(x @ w1^T + b1) -> fp16
        hgemm<128, TCE_RELU, false><<<dim3(FFd/128, 32), 512, SM128>>>(
            pxh, pw1h + (size_t)l*FFd*Dm, b1 + l*FFd, Dm, 1.f,
            nullptr, FFd, ph16, nullptr, nullptr, 0, 0, 0,
            nullptr, nullptr, nullptr, nullptr, nullptr);

        // x = BN(x + h @ w2^T + b2)
        if (l < NL-1) {
            hgemm<128, TCE_BN, true><<<dim3(Dm/128, 32), 512, SM128>>>(
                ph16, pw2h + (size_t)l*Dm*FFd, b2 + l*Dm, FFd, 1.f, px, Dm, pxh,
                nullptr, nullptr, 0, 0, 0,
                px, fg + l*Dm, fb + l*Dm, fm + l*Dm, fv + l*Dm);
        } else {
            hgemm<128, TCE_BN, false><<<dim3(Dm/128, 32), 512, SM128>>>(
                ph16, pw2h + (size_t)l*Dm*FFd, b2 + l*Dm, FFd, 1.f, out, Dm, nullptr,
                nullptr, nullptr, 0, 0, 0,
                px, fg + l*Dm, fb + l*Dm, fm + l*Dm, fv + l*Dm);
        }
    }
}

// round 16
// speedup vs baseline: 1.2169x; 1.1220x over previous
#include <cuda_runtime.h>
#include <cuda_fp16.h>
#include <cstdint>

#define Bq 8
#define Sq 512
#define Dm 1024
#define DKh 64
#define FFd 4096
#define NL 4
#define Mrows 4096

// ---------------- scratch ----------------------------------------------------
__device__ float  g_x  [(size_t)Mrows*Dm];
__device__ __half g_xh [(size_t)Mrows*Dm];
__device__ float  g_sc [(size_t)Bq*Sq*Sq];
__device__ __half g_p16[(size_t)Bq*Sq*Sq];
__device__ __half g_q16[(size_t)Mrows*DKh];
__device__ __half g_k16[(size_t)Mrows*DKh];
__device__ __half g_vt [(size_t)Bq*DKh*Sq];
__device__ __half g_hd16[(size_t)Mrows*DKh];
__device__ __half g_h16[(size_t)Mrows*FFd];
__device__ __half g_wqh[(size_t)NL*192*Dm];
__device__ __half g_w1h[(size_t)NL*FFd*Dm];
__device__ __half g_w2h[(size_t)NL*Dm*FFd];
__device__ __half g_woh[(size_t)NL*Dm*DKh];
__device__ float  g_bqkv[NL*192];

// ---------------- helpers -----------------------------------------------------
__device__ __forceinline__ uint32_t smem_u32(const void* p){
    uint32_t a;
    asm("{ .reg .u64 t; cvta.to.shared.u64 t, %1; cvt.u32.u64 %0, t; }":"=r"(a):"l"(p));
    return a;
}
__device__ __forceinline__ void cpa16(uint32_t d, const void* s){
    asm volatile("cp.async.cg.shared.global [%0], [%1], 16;"::"r"(d),"l"(s));
}
__device__ __forceinline__ void cpa_commit(){ asm volatile("cp.async.commit_group;":::"memory"); }
__device__ __forceinline__ void cpa_wait1(){ asm volatile("cp.async.wait_group 1;":::"memory"); }
__device__ __forceinline__ void cpa_wait0(){ asm volatile("cp.async.wait_group 0;":::"memory"); }

#define LDMX4(r, addr) \
    asm volatile("ldmatrix.sync.aligned.m8n8.x4.shared.b16 {%0,%1,%2,%3}, [%4];" \
        : "=r"((r)[0]),"=r"((r)[1]),"=r"((r)[2]),"=r"((r)[3]) : "r"(addr))

#define HMMA16816(c, a, b0v, b1v) \
    asm volatile("mma.sync.aligned.m16n8k16.row.col.f32.f16.f16.f32 " \
        "{%0,%1,%2,%3}, {%4,%5,%6,%7}, {%8,%9}, {%0,%1,%2,%3};" \
        : "+f"((c)[0]),"+f"((c)[1]),"+f"((c)[2]),"+f"((c)[3]) \
        : "r"((a)[0]),"r"((a)[1]),"r"((a)[2]),"r"((a)[3]), "r"(b0v),"r"(b1v))

// ---------------- fp16 HMMA GEMM  C = epi(alpha * A @ B^T) ---------------------
// 256 threads, warp grid 2(m) x 4(n), 2 CTAs/SM. A: [M,K] fp16 (batch stride sA).
// B: [N,K] fp16 (stride sB). K%64==0, M%128==0, BN_%64==0.
#define TCE_QKV   0   // +bias; route fp16 to Q / K / V^T (blockIdx.x selects)
#define TCE_SCALE 1   // *alpha -> fp32 C
#define TCE_PV    2   // fp16 Oh only
#define TCE_RELU  3   // +bias, relu -> fp16 Oh
#define TCE_BN    4   // +bias+resid, BN -> fp32 C (+fp16 Oh if WB16)

template <int BN_, int EPI, bool WB16>
__global__ void __launch_bounds__(256, 2)
hgemm(const __half* __restrict__ A, const __half* __restrict__ B,
      const float* __restrict__ bias, int K, float alpha,
      float* __restrict__ Cf, int ldc,
      __half* __restrict__ Oh, __half* __restrict__ O2, __half* __restrict__ O3,
      long sA, long sB, long sC,
      const float* __restrict__ resid,
      const float* __restrict__ gamma, const float* __restrict__ beta,
      const float* __restrict__ mean,  const float* __restrict__ var)
{
    extern __shared__ __align__(1024) char smem[];
    constexpr int STG = 16384 + BN_*128;     // A(16K) + B per stage
    constexpr int WN  = BN_/4;               // warp n-width (4 n-warps)
    constexpr int NP  = WN/16;
    constexpr int NT  = WN/8;

    A += (size_t)blockIdx.z * sA;
    B += (size_t)blockIdx.z * sB;
    if (Cf) Cf += (size_t)blockIdx.z * sC;
    if (EPI == TCE_PV) Oh += (size_t)blockIdx.z * sC;

    const uint32_t sb = smem_u32(smem);
    const int tid = threadIdx.x, wid = tid>>5, lane = tid&31;
    const int m0 = blockIdx.y*128, n0 = blockIdx.x*BN_;
    const int wm = (wid>>2)*64,    wn = (wid&3)*WN;   // 2 m-warps x 4 n-warps

    const int l15 = lane & 15, sg = lane >> 4;
    const int rA = wm + l15, rB = wn + l15;
    const uint32_t baseA = (uint32_t)rA * 128;
    const uint32_t baseB = (uint32_t)rB * 128;
    const uint32_t xorA  = ((uint32_t)(rA & 7)) << 4;
    const uint32_t xorB  = ((uint32_t)(rB & 7)) << 4;
    const uint32_t sgo   = ((uint32_t)sg) << 4;

    float acc[4][NT][4];
#pragma unroll
    for (int mt=0;mt<4;mt++)
#pragma unroll
        for (int nt=0;nt<NT;nt++)
#pragma unroll
            for (int q=0;q<4;q++) acc[mt][nt][q]=0.f;

    auto load_chunk = [&](int ck, int s){
        const int ko = ck << 6;
        const uint32_t aA = sb + s*STG;
        const uint32_t aB = aA + 16384;
#pragma unroll
        for (int i = 0; i < 4; i++) {                 // A: 128 rows x 8 segs
            int idx = tid + (i<<8); int r = idx>>3, seg = idx&7;
            uint32_t off = (r<<7)+(seg<<4), sw = off ^ ((off>>3)&0x70);
            size_t g = (size_t)(m0+r)*K + ko + (seg<<3);
            cpa16(aA+sw, A+g);
        }
#pragma unroll
        for (int i = 0; i < BN_/32; i++) {            // B: BN_ rows x 8 segs
            int idx = tid + (i<<8); int r = idx>>3, seg = idx&7;
            uint32_t off = (r<<7)+(seg<<4), sw = off ^ ((off>>3)&0x70);
            size_t g = (size_t)(n0+r)*K + ko + (seg<<3);
            cpa16(aB+sw, B+g);
        }
    };

    const int NC = K >> 6;
    load_chunk(0, 0);
    cpa_commit();

    for (int c = 0; c < NC; c++) {
        if (c+1 < NC) { load_chunk(c+1, (c+1)&1); cpa_commit(); cpa_wait1(); }
        else          { cpa_wait0(); }
        __syncthreads();

        const uint32_t aA = sb + (c&1)*STG;
        const uint32_t aB = aA + 16384;
#pragma unroll
        for (int ks = 0; ks < 4; ks++) {
            const uint32_t cA = (sgo | ((uint32_t)ks << 5)) ^ xorA;
            const uint32_t cB = (sgo | ((uint32_t)ks << 5)) ^ xorB;
            uint32_t af[4][4], bf[NP][4];
#pragma unroll
            for (int mt=0;mt<4;mt++) LDMX4(af[mt], aA + baseA + mt*2048 + cA);
#pragma unroll
            for (int np=0;np<NP;np++) LDMX4(bf[np], aB + baseB + np*2048 + cB);
#pragma unroll
            for (int mt=0;mt<4;mt++)
#pragma unroll
                for (int np=0;np<NP;np++) {
                    HMMA16816(acc[mt][2*np],   af[mt], bf[np][0], bf[np][2]);
                    HMMA16816(acc[mt][2*np+1], af[mt], bf[np][1], bf[np][3]);
                }
        }
        __syncthreads();
    }

    // ---- epilogue ----
    const int rb = m0 + wm + (lane>>2);
    const int cb = n0 + wn + (lane&3)*2;

    auto epi = [&](int row, int col, float v0, float v1){
        if (EPI == TCE_SCALE) {
            *(float2*)(Cf + (size_t)row*ldc + col) = make_float2(v0*alpha, v1*alpha);
            return;
        }
        if (EPI == TCE_PV) {
            *(__half2*)(Oh + (size_t)row*ldc + col) =
                __halves2half2(__float2half_rn(v0), __float2half_rn(v1));
            return;
        }
        v0 += bias[col]; v1 += bias[col+1];
        if (EPI == TCE_QKV) {
            __half h0 = __float2half_rn(v0), h1 = __float2half_rn(v1);
            if (blockIdx.x < 2) {
                __half* dst = (blockIdx.x == 0) ? Oh : O2;
                *(__half2*)(dst + (size_t)row*DKh + (col & 63)) = __halves2half2(h0, h1);
            } else {
                int b = row >> 9, mi = row & 511;
                O3[((size_t)b*DKh + (col-128))*Sq + mi] = h0;
                O3[((size_t)b*DKh + (col-127))*Sq + mi] = h1;
            }
            return;
        }
        if (EPI == TCE_RELU) { v0 = fmaxf(v0, 0.f); v1 = fmaxf(v1, 0.f); }
        if (EPI == TCE_BN) {
            float2 rs = *(const float2*)(resid + (size_t)row*ldc + col);
            v0 += rs.x; v1 += rs.y;
            v0 = gamma[col]  *(v0 - mean[col])  *rsqrtf(var[col]  +1e-3f) + beta[col];
            v1 = gamma[col+1]*(v1 - mean[col+1])*rsqrtf(var[col+1]+1e-3f) + beta[col+1];
        }
        if (EPI != TCE_RELU)
            *(float2*)(Cf + (size_t)row*ldc + col) = make_float2(v0, v1);
        if (WB16 || EPI == TCE_RELU)
            *(__half2*)(Oh + (size_t)row*ldc + col) =
                __halves2half2(__float2half_rn(v0), __float2half_rn(v1));
    };

#pragma unroll
    for (int mt=0;mt<4;mt++)
#pragma unroll
        for (int nt=0;nt<NT;nt++) {
            const int col = cb + nt*8;
            epi(rb + mt*16,     col, acc[mt][nt][0], acc[mt][nt][1]);
            epi(rb + mt*16 + 8, col, acc[mt][nt][2], acc[mt][nt][3]);
        }
}

// ------ vectorized transpose to fp16: in[K,N] -> out[N,K], batched over z ------
__global__ void whalfT(const float* __restrict__ in, int K, int N,
                       long inS, __half* __restrict__ out, long outS)
{
    __shared__ float t[64][33];
    in  += (size_t)blockIdx.z * inS;
    out += (size_t)blockIdx.z * outS;
    const int k0 = blockIdx.x*64, n0 = blockIdx.y*32;
    const int tx = threadIdx.x, ty = threadIdx.y;
#pragma unroll
    for (int r = ty; r < 64; r += 8)
        t[r][tx] = in[(size_t)(k0+r)*N + n0 + tx];
    __syncthreads();
#pragma unroll
    for (int j = ty; j < 32; j += 8) {
        __half2 v = __halves2half2(__float2half_rn(t[2*tx][j]),
                                   __float2half_rn(t[2*tx+1][j]));
        *(__half2*)(out + (size_t)(n0+j)*K + k0 + 2*tx) = v;
    }
}

// QKV weights: [Dm, DKh] x 3 matrices x NL layers -> packed [192, Dm] per layer
__global__ void whalfT_qkv(const float* __restrict__ wq, const float* __restrict__ wk,
                           const float* __restrict__ wv, __half* __restrict__ out)
{
    __shared__ float t[64][33];
    const int mat = blockIdx.y >> 1;
    const int l = blockIdx.z;
    const float* in = ((mat == 0) ? wq : (mat == 1) ? wk : wv) + (size_t)l*Dm*DKh;
    __half* o = out + (size_t)l*192*Dm + (size_t)mat*DKh*Dm;
    const int k0 = blockIdx.x*64, n0 = (blockIdx.y & 1)*32;
    const int tx = threadIdx.x, ty = threadIdx.y;
#pragma unroll
    for (int r = ty; r < 64; r += 8)
        t[r][tx] = in[(size_t)(k0+r)*DKh + n0 + tx];
    __syncthreads();
#pragma unroll
    for (int j = ty; j < 32; j += 8) {
        __half2 v = __halves2half2(__float2half_rn(t[2*tx][j]),
                                   __float2half_rn(t[2*tx+1][j]));
        *(__half2*)(o + (size_t)(n0+j)*Dm + k0 + 2*tx) = v;
    }
}

__global__ void biaspack(const float* bq, const float* bk, const float* bv, float* o)
{
    int t = threadIdx.x + blockIdx.x*256;
    if (t >= NL*192) return;
    int l = t/192, j = t%192;
    o[t] = (j < 64) ? bq[l*64+j] : (j < 128) ? bk[l*64+j-64] : bv[l*64+j-128];
}

// ---------------- embed + fp16 ------------------------------------------------
__global__ void embed_k(const int* __restrict__ seq, const float* __restrict__ emb,
                        const float* __restrict__ pes, float* __restrict__ x,
                        __half* __restrict__ xh)
{
    size_t idx = (size_t)blockIdx.x*256 + threadIdx.x;
    int d = (int)(idx & (Dm-1));
    size_t bs = idx >> 10;
    int s = (int)(bs & (Sq-1));
    float v = emb[(size_t)seq[bs]*Dm + d] + pes[(size_t)s*Dm];
    x[idx] = v;
    xh[idx] = __float2half_rn(v);
}

// -------- softmax: one warp per 512-col row, shfl-only, fp32 -> fp16 -----------
__global__ void softmax_w(const float* __restrict__ S, __half* __restrict__ P)
{
    const int row  = blockIdx.x*8 + (threadIdx.x >> 5);
    const int lane = threadIdx.x & 31;
    const float* p = S + (size_t)row*Sq;
    __half* o = P + (size_t)row*Sq;

    float4 v[4];
#pragma unroll
    for (int i = 0; i < 4; i++)
        v[i] = *(const float4*)(p + i*128 + lane*4);

    float mx = -1e30f;
#pragma unroll
    for (int i = 0; i < 4; i++)
        mx = fmaxf(mx, fmaxf(fmaxf(v[i].x, v[i].y), fmaxf(v[i].z, v[i].w)));
#pragma unroll
    for (int ofs = 16; ofs > 0; ofs >>= 1)
        mx = fmaxf(mx, __shfl_xor_sync(0xffffffffu, mx, ofs));

    float sum = 0.f;
#pragma unroll
    for (int i = 0; i < 4; i++) {
        v[i].x = __expf(v[i].x - mx); v[i].y = __expf(v[i].y - mx);
        v[i].z = __expf(v[i].z - mx); v[i].w = __expf(v[i].w - mx);
        sum += v[i].x + v[i].y + v[i].z + v[i].w;
    }
#pragma unroll
    for (int ofs = 16; ofs > 0; ofs >>= 1)
        sum += __shfl_xor_sync(0xffffffffu, sum, ofs);
    const float inv = 1.f / sum;

#pragma unroll
    for (int i = 0; i < 4; i++) {
        __half2 h0 = __halves2half2(__float2half_rn(v[i].x*inv), __float2half_rn(v[i].y*inv));
        __half2 h1 = __halves2half2(__float2half_rn(v[i].z*inv), __float2half_rn(v[i].w*inv));
        *(__half2*)(o + i*128 + lane*4)     = h0;
        *(__half2*)(o + i*128 + lane*4 + 2) = h1;
    }
}

// ---------------- host ----------------------------------------------------------
static const int SM64  = 2*(16384 + 64*128);     // 49152
static const int SM128 = 2*(16384 + 128*128);    // 65536

extern "C" void kernel_launch(void* const* d_in, const int* in_sizes, int n_in,
                              void* d_out, int out_size)
{
    const int*   seq = (const int*)  d_in[0];
    const float* emb = (const float*)d_in[1];
    const float* pes = (const float*)d_in[2];
    const float* wq  = (const float*)d_in[3];
    const float* bqp = (const float*)d_in[4];
    const float* wk  = (const float*)d_in[5];
    const float* bkp = (const float*)d_in[6];
    const float* wv  = (const float*)d_in[7];
    const float* bvp = (const float*)d_in[8];
    const float* wo  = (const float*)d_in[9];
    const float* bo  = (const float*)d_in[10];
    const float* ag  = (const float*)d_in[11];
    const float* ab  = (const float*)d_in[12];
    const float* am  = (const float*)d_in[13];
    const float* avv = (const float*)d_in[14];
    const float* w1  = (const float*)d_in[15];
    const float* b1  = (const float*)d_in[16];
    const float* w2  = (const float*)d_in[17];
    const float* b2  = (const float*)d_in[18];
    const float* fg  = (const float*)d_in[19];
    const float* fb  = (const float*)d_in[20];
    const float* fm  = (const float*)d_in[21];
    const float* fv  = (const float*)d_in[22];
    float* out = (float*)d_out;

    float *px, *psc, *pbq;
    __half *pxh, *pp16, *pq16, *pk16, *pvt, *phd16, *ph16, *pwqh, *pw1h, *pw2h, *pwoh;
    cudaGetSymbolAddress((void**)&px,    g_x);
    cudaGetSymbolAddress((void**)&pxh,   g_xh);
    cudaGetSymbolAddress((void**)&psc,   g_sc);
    cudaGetSymbolAddress((void**)&pp16,  g_p16);
    cudaGetSymbolAddress((void**)&pq16,  g_q16);
    cudaGetSymbolAddress((void**)&pk16,  g_k16);
    cudaGetSymbolAddress((void**)&pvt,   g_vt);
    cudaGetSymbolAddress((void**)&phd16, g_hd16);
    cudaGetSymbolAddress((void**)&ph16,  g_h16);
    cudaGetSymbolAddress((void**)&pwqh,  g_wqh);
    cudaGetSymbolAddress((void**)&pw1h,  g_w1h);
    cudaGetSymbolAddress((void**)&pw2h,  g_w2h);
    cudaGetSymbolAddress((void**)&pwoh,  g_woh);
    cudaGetSymbolAddress((void**)&pbq,   g_bqkv);

    cudaFuncSetAttribute(hgemm<64,  TCE_QKV,   false>, cudaFuncAttributeMaxDynamicSharedMemorySize, SM64);
    cudaFuncSetAttribute(hgemm<128, TCE_SCALE, false>, cudaFuncAttributeMaxDynamicSharedMemorySize, SM128);
    cudaFuncSetAttribute(hgemm<64,  TCE_PV,    false>, cudaFuncAttributeMaxDynamicSharedMemorySize, SM64);
    cudaFuncSetAttribute(hgemm<128, TCE_RELU,  false>, cudaFuncAttributeMaxDynamicSharedMemorySize, SM128);
    cudaFuncSetAttribute(hgemm<128, TCE_BN,    true >, cudaFuncAttributeMaxDynamicSharedMemorySize, SM128);
    cudaFuncSetAttribute(hgemm<128, TCE_BN,    false>, cudaFuncAttributeMaxDynamicSharedMemorySize, SM128);

    static cudaStream_t s2 = nullptr;
    static cudaEvent_t evF = nullptr, evQ = nullptr, evJ = nullptr;
    if (!s2) {
        cudaStreamCreateWithFlags(&s2, cudaStreamNonBlocking);
        cudaEventCreateWithFlags(&evF, cudaEventDisableTiming);
        cudaEventCreateWithFlags(&evQ, cudaEventDisableTiming);
        cudaEventCreateWithFlags(&evJ, cudaEventDisableTiming);
    }

    dim3 tb(32, 8);

    // fork immediately: ALL weight prep runs on s2, overlapping embed + layer-0
    cudaEventRecord(evF, 0);
    cudaStreamWaitEvent(s2, evF, 0);
    whalfT_qkv<<<dim3(Dm/64, 6, NL), tb, 0, s2>>>(wq, wk, wv, pwqh);
    biaspack<<<3, 256, 0, s2>>>(bqp, bkp, bvp, pbq);
    cudaEventRecord(evQ, s2);
    whalfT<<<dim3(1, Dm/32, NL), tb, 0, s2>>>(wo, DKh, Dm, (long)DKh*Dm, pwoh, (long)Dm*DKh);
    whalfT<<<dim3(Dm/64, FFd/32, NL), tb, 0, s2>>>(w1, Dm, FFd, (long)Dm*FFd, pw1h, (long)FFd*Dm);
    whalfT<<<dim3(FFd/64, Dm/32, NL), tb, 0, s2>>>(w2, FFd, Dm, (long)FFd*Dm, pw2h, (long)Dm*FFd);
    cudaEventRecord(evJ, s2);

    // main: embed, then wait for QKV weights
    embed_k<<<(Mrows*Dm)/256, 256>>>(seq, emb, pes, px, pxh);
    cudaStreamWaitEvent(0, evQ, 0);

    bool joined = false;
    for (int l = 0; l < NL; l++) {
        // QKV fused: writes fp16 Q, K, V^T
        hgemm<64, TCE_QKV, false><<<dim3(3, 32), 256, SM64>>>(
            pxh, pwqh + (size_t)l*192*Dm, pbq + l*192, Dm, 1.f,
            nullptr, 0, pq16, pk16, pvt, 0, 0, 0,
            nullptr, nullptr, nullptr, nullptr, nullptr);

        // scores = Q @ K^T / 8 (batched) -> fp32
        hgemm<128, TCE_SCALE, false><<<dim3(4, 4, Bq), 256, SM128>>>(
            pq16, pk16, nullptr, DKh, 0.125f, psc, Sq, nullptr, nullptr, nullptr,
            (long)Sq*DKh, (long)Sq*DKh, (long)Sq*Sq,
            nullptr, nullptr, nullptr, nullptr, nullptr);

        softmax_w<<<Mrows/8, 256>>>(psc, pp16);

        // head = P @ (V^T)^T (batched) -> fp16
        hgemm<64, TCE_PV, false><<<dim3(1, 4, Bq), 256, SM64>>>(
            pp16, pvt, nullptr, Sq, 1.f, nullptr, DKh, phd16, nullptr, nullptr,
            (long)Sq*Sq, (long)DKh*Sq, (long)Sq*DKh,
            nullptr, nullptr, nullptr, nullptr, nullptr);

        if (!joined) { cudaStreamWaitEvent(0, evJ, 0); joined = true; }

        // x = BN(x + head @ wo^T + bo) -> fp32 x + fp16 xh
        hgemm<128, TCE_BN, true><<<dim3(8, 32), 256, SM128>>>(
            phd16, pwoh + (size_t)l*Dm*DKh, bo + l*Dm, DKh, 1.f, px, Dm, pxh,
            nullptr, nullptr, 0, 0, 0,
            px, ag + l*Dm, ab + l*Dm, am + l*Dm, avv + l*Dm);

        // h = relu(x @ w1^T + b1) -> fp16
        hgemm<128, TCE_RELU, false><<<dim3(FFd/128, 32), 256, SM128>>>(
            pxh, pw1h + (size_t)l*FFd*Dm, b1 + l*FFd, Dm, 1.f,
            nullptr, FFd, ph16, nullptr, nullptr, 0, 0, 0,
            nullptr, nullptr, nullptr, nullptr, nullptr);

        // x = BN(x + h @ w2^T + b2)
        if (l < NL-1) {
            hgemm<128, TCE_BN, true><<<dim3(Dm/128, 32), 256, SM128>>>(
                ph16, pw2h + (size_t)l*Dm*FFd, b2 + l*Dm, FFd, 1.f, px, Dm, pxh,
                nullptr, nullptr, 0, 0, 0,
                px, fg + l*Dm, fb + l*Dm, fm + l*Dm, fv + l*Dm);
        } else {
            hgemm<128, TCE_BN, false><<<dim3(Dm/128, 32), 256, SM128>>>(
                ph16, pw2h + (size_t)l*Dm*FFd, b2 + l*Dm, FFd, 1.f, out, Dm, nullptr,
                nullptr, nullptr, 0, 0, 0,
                px, fg + l*Dm, fb + l*Dm, fm + l*Dm, fv + l*Dm);
        }
    }
}

// round 17
// speedup vs baseline: 1.2259x; 1.0074x over previous
#include <cuda_runtime.h>
#include <cuda_fp16.h>
#include <cstdint>

#define Bq 8
#define Sq 512
#define Dm 1024
#define DKh 64
#define FFd 4096
#define NL 4
#define Mrows 4096

// ---------------- scratch ----------------------------------------------------
__device__ float  g_x  [(size_t)Mrows*Dm];
__device__ __half g_xh [(size_t)Mrows*Dm];
__device__ float  g_sc [(size_t)Bq*Sq*Sq];
__device__ __half g_p16[(size_t)Bq*Sq*Sq];
__device__ __half g_q16[(size_t)Mrows*DKh];
__device__ __half g_k16[(size_t)Mrows*DKh];
__device__ __half g_vt [(size_t)Bq*DKh*Sq];
__device__ __half g_hd16[(size_t)Mrows*DKh];
__device__ __half g_h16[(size_t)Mrows*FFd];
__device__ __half g_wqh[(size_t)NL*192*Dm];
__device__ __half g_w1h[(size_t)NL*FFd*Dm];
__device__ __half g_w2h[(size_t)NL*Dm*FFd];
__device__ __half g_woh[(size_t)NL*Dm*DKh];
__device__ float  g_bqkv[NL*192];

// ---------------- helpers -----------------------------------------------------
__device__ __forceinline__ uint32_t smem_u32(const void* p){
    uint32_t a;
    asm("{ .reg .u64 t; cvta.to.shared.u64 t, %1; cvt.u32.u64 %0, t; }":"=r"(a):"l"(p));
    return a;
}
__device__ __forceinline__ void cpa16(uint32_t d, const void* s){
    asm volatile("cp.async.cg.shared.global [%0], [%1], 16;"::"r"(d),"l"(s));
}
__device__ __forceinline__ void cpa_commit(){ asm volatile("cp.async.commit_group;":::"memory"); }
__device__ __forceinline__ void cpa_wait1(){ asm volatile("cp.async.wait_group 1;":::"memory"); }
__device__ __forceinline__ void cpa_wait0(){ asm volatile("cp.async.wait_group 0;":::"memory"); }

#define LDMX4(r, addr) \
    asm volatile("ldmatrix.sync.aligned.m8n8.x4.shared.b16 {%0,%1,%2,%3}, [%4];" \
        : "=r"((r)[0]),"=r"((r)[1]),"=r"((r)[2]),"=r"((r)[3]) : "r"(addr))

#define HMMA16816(c, a, b0v, b1v) \
    asm volatile("mma.sync.aligned.m16n8k16.row.col.f32.f16.f16.f32 " \
        "{%0,%1,%2,%3}, {%4,%5,%6,%7}, {%8,%9}, {%0,%1,%2,%3};" \
        : "+f"((c)[0]),"+f"((c)[1]),"+f"((c)[2]),"+f"((c)[3]) \
        : "r"((a)[0]),"r"((a)[1]),"r"((a)[2]),"r"((a)[3]), "r"(b0v),"r"(b1v))

// ---------------- fp16 HMMA GEMM  C = epi(alpha * A @ B^T) ---------------------
// 256 threads, warp grid 2(m) x 4(n), 2 CTAs/SM. A: [M,K] fp16 (batch stride sA).
// B: [N,K] fp16 (stride sB). K%64==0, M%128==0, BN_%64==0.
#define TCE_QKV   0
#define TCE_SCALE 1
#define TCE_PV    2
#define TCE_RELU  3
#define TCE_BN    4

template <int BN_, int EPI, bool WB16>
__global__ void __launch_bounds__(256, 2)
hgemm(const __half* __restrict__ A, const __half* __restrict__ B,
      const float* __restrict__ bias, int K, float alpha,
      float* __restrict__ Cf, int ldc,
      __half* __restrict__ Oh, __half* __restrict__ O2, __half* __restrict__ O3,
      long sA, long sB, long sC,
      const float* __restrict__ resid,
      const float* __restrict__ gamma, const float* __restrict__ beta,
      const float* __restrict__ mean,  const float* __restrict__ var)
{
    extern __shared__ __align__(1024) char smem[];
    constexpr int STG = 16384 + BN_*128;
    constexpr int WN  = BN_/4;
    constexpr int NP  = WN/16;
    constexpr int NT  = WN/8;

    A += (size_t)blockIdx.z * sA;
    B += (size_t)blockIdx.z * sB;
    if (Cf) Cf += (size_t)blockIdx.z * sC;
    if (EPI == TCE_PV) Oh += (size_t)blockIdx.z * sC;

    const uint32_t sb = smem_u32(smem);
    const int tid = threadIdx.x, wid = tid>>5, lane = tid&31;
    const int m0 = blockIdx.y*128, n0 = blockIdx.x*BN_;
    const int wm = (wid>>2)*64,    wn = (wid&3)*WN;

    const int l15 = lane & 15, sg = lane >> 4;
    const int rA = wm + l15, rB = wn + l15;
    const uint32_t baseA = (uint32_t)rA * 128;
    const uint32_t baseB = (uint32_t)rB * 128;
    const uint32_t xorA  = ((uint32_t)(rA & 7)) << 4;
    const uint32_t xorB  = ((uint32_t)(rB & 7)) << 4;
    const uint32_t sgo   = ((uint32_t)sg) << 4;

    float acc[4][NT][4];
#pragma unroll
    for (int mt=0;mt<4;mt++)
#pragma unroll
        for (int nt=0;nt<NT;nt++)
#pragma unroll
            for (int q=0;q<4;q++) acc[mt][nt][q]=0.f;

    auto load_chunk = [&](int ck, int s){
        const int ko = ck << 6;
        const uint32_t aA = sb + s*STG;
        const uint32_t aB = aA + 16384;
#pragma unroll
        for (int i = 0; i < 4; i++) {
            int idx = tid + (i<<8); int r = idx>>3, seg = idx&7;
            uint32_t off = (r<<7)+(seg<<4), sw = off ^ ((off>>3)&0x70);
            size_t g = (size_t)(m0+r)*K + ko + (seg<<3);
            cpa16(aA+sw, A+g);
        }
#pragma unroll
        for (int i = 0; i < BN_/32; i++) {
            int idx = tid + (i<<8); int r = idx>>3, seg = idx&7;
            uint32_t off = (r<<7)+(seg<<4), sw = off ^ ((off>>3)&0x70);
            size_t g = (size_t)(n0+r)*K + ko + (seg<<3);
            cpa16(aB+sw, B+g);
        }
    };

    const int NC = K >> 6;
    load_chunk(0, 0);
    cpa_commit();

    for (int c = 0; c < NC; c++) {
        if (c+1 < NC) { load_chunk(c+1, (c+1)&1); cpa_commit(); cpa_wait1(); }
        else          { cpa_wait0(); }
        __syncthreads();

        const uint32_t aA = sb + (c&1)*STG;
        const uint32_t aB = aA + 16384;
#pragma unroll
        for (int ks = 0; ks < 4; ks++) {
            const uint32_t cA = (sgo | ((uint32_t)ks << 5)) ^ xorA;
            const uint32_t cB = (sgo | ((uint32_t)ks << 5)) ^ xorB;
            uint32_t af[4][4], bf[NP][4];
#pragma unroll
            for (int mt=0;mt<4;mt++) LDMX4(af[mt], aA + baseA + mt*2048 + cA);
#pragma unroll
            for (int np=0;np<NP;np++) LDMX4(bf[np], aB + baseB + np*2048 + cB);
#pragma unroll
            for (int mt=0;mt<4;mt++)
#pragma unroll
                for (int np=0;np<NP;np++) {
                    HMMA16816(acc[mt][2*np],   af[mt], bf[np][0], bf[np][2]);
                    HMMA16816(acc[mt][2*np+1], af[mt], bf[np][1], bf[np][3]);
                }
        }
        __syncthreads();
    }

    // ---- epilogue ----
    const int rb = m0 + wm + (lane>>2);
    const int cb = n0 + wn + (lane&3)*2;

    auto epi = [&](int row, int col, float v0, float v1){
        if (EPI == TCE_SCALE) {
            *(float2*)(Cf + (size_t)row*ldc + col) = make_float2(v0*alpha, v1*alpha);
            return;
        }
        if (EPI == TCE_PV) {
            *(__half2*)(Oh + (size_t)row*ldc + col) =
                __halves2half2(__float2half_rn(v0), __float2half_rn(v1));
            return;
        }
        v0 += bias[col]; v1 += bias[col+1];
        if (EPI == TCE_QKV) {
            __half h0 = __float2half_rn(v0), h1 = __float2half_rn(v1);
            if (blockIdx.x < 2) {
                __half* dst = (blockIdx.x == 0) ? Oh : O2;
                *(__half2*)(dst + (size_t)row*DKh + (col & 63)) = __halves2half2(h0, h1);
            } else {
                int b = row >> 9, mi = row & 511;
                O3[((size_t)b*DKh + (col-128))*Sq + mi] = h0;
                O3[((size_t)b*DKh + (col-127))*Sq + mi] = h1;
            }
            return;
        }
        if (EPI == TCE_RELU) { v0 = fmaxf(v0, 0.f); v1 = fmaxf(v1, 0.f); }
        if (EPI == TCE_BN) {
            float2 rs = *(const float2*)(resid + (size_t)row*ldc + col);
            v0 += rs.x; v1 += rs.y;
            v0 = gamma[col]  *(v0 - mean[col])  *rsqrtf(var[col]  +1e-3f) + beta[col];
            v1 = gamma[col+1]*(v1 - mean[col+1])*rsqrtf(var[col+1]+1e-3f) + beta[col+1];
        }
        if (EPI != TCE_RELU)
            *(float2*)(Cf + (size_t)row*ldc + col) = make_float2(v0, v1);
        if (WB16 || EPI == TCE_RELU)
            *(__half2*)(Oh + (size_t)row*ldc + col) =
                __halves2half2(__float2half_rn(v0), __float2half_rn(v1));
    };

#pragma unroll
    for (int mt=0;mt<4;mt++)
#pragma unroll
        for (int nt=0;nt<NT;nt++) {
            const int col = cb + nt*8;
            epi(rb + mt*16,     col, acc[mt][nt][0], acc[mt][nt][1]);
            epi(rb + mt*16 + 8, col, acc[mt][nt][2], acc[mt][nt][3]);
        }
}

// ------ vectorized transpose to fp16: in[K,N] -> out[N,K], batched over z ------
__global__ void whalfT(const float* __restrict__ in, int K, int N,
                       long inS, __half* __restrict__ out, long outS)
{
    __shared__ float t[64][33];
    in  += (size_t)blockIdx.z * inS;
    out += (size_t)blockIdx.z * outS;
    const int k0 = blockIdx.x*64, n0 = blockIdx.y*32;
    const int tx = threadIdx.x, ty = threadIdx.y;
#pragma unroll
    for (int r = ty; r < 64; r += 8)
        t[r][tx] = in[(size_t)(k0+r)*N + n0 + tx];
    __syncthreads();
#pragma unroll
    for (int j = ty; j < 32; j += 8) {
        __half2 v = __halves2half2(__float2half_rn(t[2*tx][j]),
                                   __float2half_rn(t[2*tx+1][j]));
        *(__half2*)(out + (size_t)(n0+j)*K + k0 + 2*tx) = v;
    }
}

// QKV weights: [Dm, DKh] x 3 matrices x NL layers -> packed [192, Dm] per layer
__global__ void whalfT_qkv(const float* __restrict__ wq, const float* __restrict__ wk,
                           const float* __restrict__ wv, __half* __restrict__ out)
{
    __shared__ float t[64][33];
    const int mat = blockIdx.y >> 1;
    const int l = blockIdx.z;
    const float* in = ((mat == 0) ? wq : (mat == 1) ? wk : wv) + (size_t)l*Dm*DKh;
    __half* o = out + (size_t)l*192*Dm + (size_t)mat*DKh*Dm;
    const int k0 = blockIdx.x*64, n0 = (blockIdx.y & 1)*32;
    const int tx = threadIdx.x, ty = threadIdx.y;
#pragma unroll
    for (int r = ty; r < 64; r += 8)
        t[r][tx] = in[(size_t)(k0+r)*DKh + n0 + tx];
    __syncthreads();
#pragma unroll
    for (int j = ty; j < 32; j += 8) {
        __half2 v = __halves2half2(__float2half_rn(t[2*tx][j]),
                                   __float2half_rn(t[2*tx+1][j]));
        *(__half2*)(o + (size_t)(n0+j)*Dm + k0 + 2*tx) = v;
    }
}

__global__ void biaspack(const float* bq, const float* bk, const float* bv, float* o)
{
    int t = threadIdx.x + blockIdx.x*256;
    if (t >= NL*192) return;
    int l = t/192, j = t%192;
    o[t] = (j < 64) ? bq[l*64+j] : (j < 128) ? bk[l*64+j-64] : bv[l*64+j-128];
}

// ---------------- embed + fp16 (vectorized: 4 elems/thread) --------------------
__global__ void embed_k(const int* __restrict__ seq, const float* __restrict__ emb,
                        const float* __restrict__ pes, float* __restrict__ x,
                        __half* __restrict__ xh)
{
    size_t e4 = (size_t)blockIdx.x*256 + threadIdx.x;   // float4 index
    size_t idx = e4 << 2;
    int d = (int)(idx & (Dm-1));
    size_t bs = idx >> 10;
    int s = (int)(bs & (Sq-1));
    float p = pes[(size_t)s*Dm];
    float4 v = *(const float4*)(emb + (size_t)seq[bs]*Dm + d);
    v.x += p; v.y += p; v.z += p; v.w += p;
    *(float4*)(x + idx) = v;
    __half2 h0 = __halves2half2(__float2half_rn(v.x), __float2half_rn(v.y));
    __half2 h1 = __halves2half2(__float2half_rn(v.z), __float2half_rn(v.w));
    *(__half2*)(xh + idx)     = h0;
    *(__half2*)(xh + idx + 2) = h1;
}

// -------- softmax: one warp per 512-col row, shfl-only, fp32 -> fp16 -----------
__global__ void softmax_w(const float* __restrict__ S, __half* __restrict__ P)
{
    const int row  = blockIdx.x*8 + (threadIdx.x >> 5);
    const int lane = threadIdx.x & 31;
    const float* p = S + (size_t)row*Sq;
    __half* o = P + (size_t)row*Sq;

    float4 v[4];
#pragma unroll
    for (int i = 0; i < 4; i++)
        v[i] = *(const float4*)(p + i*128 + lane*4);

    float mx = -1e30f;
#pragma unroll
    for (int i = 0; i < 4; i++)
        mx = fmaxf(mx, fmaxf(fmaxf(v[i].x, v[i].y), fmaxf(v[i].z, v[i].w)));
#pragma unroll
    for (int ofs = 16; ofs > 0; ofs >>= 1)
        mx = fmaxf(mx, __shfl_xor_sync(0xffffffffu, mx, ofs));

    float sum = 0.f;
#pragma unroll
    for (int i = 0; i < 4; i++) {
        v[i].x = __expf(v[i].x - mx); v[i].y = __expf(v[i].y - mx);
        v[i].z = __expf(v[i].z - mx); v[i].w = __expf(v[i].w - mx);
        sum += v[i].x + v[i].y + v[i].z + v[i].w;
    }
#pragma unroll
    for (int ofs = 16; ofs > 0; ofs >>= 1)
        sum += __shfl_xor_sync(0xffffffffu, sum, ofs);
    const float inv = 1.f / sum;

#pragma unroll
    for (int i = 0; i < 4; i++) {
        __half2 h0 = __halves2half2(__float2half_rn(v[i].x*inv), __float2half_rn(v[i].y*inv));
        __half2 h1 = __halves2half2(__float2half_rn(v[i].z*inv), __float2half_rn(v[i].w*inv));
        *(__half2*)(o + i*128 + lane*4)     = h0;
        *(__half2*)(o + i*128 + lane*4 + 2) = h1;
    }
}

// ---------------- host ----------------------------------------------------------
static const int SM64  = 2*(16384 + 64*128);     // 49152
static const int SM128 = 2*(16384 + 128*128);    // 65536

extern "C" void kernel_launch(void* const* d_in, const int* in_sizes, int n_in,
                              void* d_out, int out_size)
{
    const int*   seq = (const int*)  d_in[0];
    const float* emb = (const float*)d_in[1];
    const float* pes = (const float*)d_in[2];
    const float* wq  = (const float*)d_in[3];
    const float* bqp = (const float*)d_in[4];
    const float* wk  = (const float*)d_in[5];
    const float* bkp = (const float*)d_in[6];
    const float* wv  = (const float*)d_in[7];
    const float* bvp = (const float*)d_in[8];
    const float* wo  = (const float*)d_in[9];
    const float* bo  = (const float*)d_in[10];
    const float* ag  = (const float*)d_in[11];
    const float* ab  = (const float*)d_in[12];
    const float* am  = (const float*)d_in[13];
    const float* avv = (const float*)d_in[14];
    const float* w1  = (const float*)d_in[15];
    const float* b1  = (const float*)d_in[16];
    const float* w2  = (const float*)d_in[17];
    const float* b2  = (const float*)d_in[18];
    const float* fg  = (const float*)d_in[19];
    const float* fb  = (const float*)d_in[20];
    const float* fm  = (const float*)d_in[21];
    const float* fv  = (const float*)d_in[22];
    float* out = (float*)d_out;

    float *px, *psc, *pbq;
    __half *pxh, *pp16, *pq16, *pk16, *pvt, *phd16, *ph16, *pwqh, *pw1h, *pw2h, *pwoh;
    cudaGetSymbolAddress((void**)&px,    g_x);
    cudaGetSymbolAddress((void**)&pxh,   g_xh);
    cudaGetSymbolAddress((void**)&psc,   g_sc);
    cudaGetSymbolAddress((void**)&pp16,  g_p16);
    cudaGetSymbolAddress((void**)&pq16,  g_q16);
    cudaGetSymbolAddress((void**)&pk16,  g_k16);
    cudaGetSymbolAddress((void**)&pvt,   g_vt);
    cudaGetSymbolAddress((void**)&phd16, g_hd16);
    cudaGetSymbolAddress((void**)&ph16,  g_h16);
    cudaGetSymbolAddress((void**)&pwqh,  g_wqh);
    cudaGetSymbolAddress((void**)&pw1h,  g_w1h);
    cudaGetSymbolAddress((void**)&pw2h,  g_w2h);
    cudaGetSymbolAddress((void**)&pwoh,  g_woh);
    cudaGetSymbolAddress((void**)&pbq,   g_bqkv);

    cudaFuncSetAttribute(hgemm<64,  TCE_QKV,   false>, cudaFuncAttributeMaxDynamicSharedMemorySize, SM64);
    cudaFuncSetAttribute(hgemm<128, TCE_SCALE, false>, cudaFuncAttributeMaxDynamicSharedMemorySize, SM128);
    cudaFuncSetAttribute(hgemm<64,  TCE_PV,    false>, cudaFuncAttributeMaxDynamicSharedMemorySize, SM64);
    cudaFuncSetAttribute(hgemm<128, TCE_RELU,  false>, cudaFuncAttributeMaxDynamicSharedMemorySize, SM128);
    cudaFuncSetAttribute(hgemm<128, TCE_BN,    true >, cudaFuncAttributeMaxDynamicSharedMemorySize, SM128);
    cudaFuncSetAttribute(hgemm<128, TCE_BN,    false>, cudaFuncAttributeMaxDynamicSharedMemorySize, SM128);

    static cudaStream_t s2 = nullptr;
    static cudaEvent_t evF = nullptr, evQ = nullptr, evO = nullptr, evW1 = nullptr, evW2 = nullptr;
    if (!s2) {
        cudaStreamCreateWithFlags(&s2, cudaStreamNonBlocking);
        cudaEventCreateWithFlags(&evF,  cudaEventDisableTiming);
        cudaEventCreateWithFlags(&evQ,  cudaEventDisableTiming);
        cudaEventCreateWithFlags(&evO,  cudaEventDisableTiming);
        cudaEventCreateWithFlags(&evW1, cudaEventDisableTiming);
        cudaEventCreateWithFlags(&evW2, cudaEventDisableTiming);
    }

    dim3 tb(32, 8);

    // fork: prep ordered by first use (QKV -> wo -> w1 -> w2), events after each
    cudaEventRecord(evF, 0);
    cudaStreamWaitEvent(s2, evF, 0);
    whalfT_qkv<<<dim3(Dm/64, 6, NL), tb, 0, s2>>>(wq, wk, wv, pwqh);
    biaspack<<<3, 256, 0, s2>>>(bqp, bkp, bvp, pbq);
    cudaEventRecord(evQ, s2);
    whalfT<<<dim3(1, Dm/32, NL), tb, 0, s2>>>(wo, DKh, Dm, (long)DKh*Dm, pwoh, (long)Dm*DKh);
    cudaEventRecord(evO, s2);
    whalfT<<<dim3(Dm/64, FFd/32, NL), tb, 0, s2>>>(w1, Dm, FFd, (long)Dm*FFd, pw1h, (long)FFd*Dm);
    cudaEventRecord(evW1, s2);
    whalfT<<<dim3(FFd/64, Dm/32, NL), tb, 0, s2>>>(w2, FFd, Dm, (long)FFd*Dm, pw2h, (long)Dm*FFd);
    cudaEventRecord(evW2, s2);

    // main: embed, then wait for QKV weights only
    embed_k<<<(Mrows*Dm)/1024, 256>>>(seq, emb, pes, px, pxh);
    cudaStreamWaitEvent(0, evQ, 0);

    for (int l = 0; l < NL; l++) {
        // QKV fused: writes fp16 Q, K, V^T
        hgemm<64, TCE_QKV, false><<<dim3(3, 32), 256, SM64>>>(
            pxh, pwqh + (size_t)l*192*Dm, pbq + l*192, Dm, 1.f,
            nullptr, 0, pq16, pk16, pvt, 0, 0, 0,
            nullptr, nullptr, nullptr, nullptr, nullptr);

        // scores = Q @ K^T / 8 (batched) -> fp32
        hgemm<128, TCE_SCALE, false><<<dim3(4, 4, Bq), 256, SM128>>>(
            pq16, pk16, nullptr, DKh, 0.125f, psc, Sq, nullptr, nullptr, nullptr,
            (long)Sq*DKh, (long)Sq*DKh, (long)Sq*Sq,
            nullptr, nullptr, nullptr, nullptr, nullptr);

        softmax_w<<<Mrows/8, 256>>>(psc, pp16);

        // head = P @ (V^T)^T (batched) -> fp16
        hgemm<64, TCE_PV, false><<<dim3(1, 4, Bq), 256, SM64>>>(
            pp16, pvt, nullptr, Sq, 1.f, nullptr, DKh, phd16, nullptr, nullptr,
            (long)Sq*Sq, (long)DKh*Sq, (long)Sq*DKh,
            nullptr, nullptr, nullptr, nullptr, nullptr);

        if (l == 0) cudaStreamWaitEvent(0, evO, 0);

        // x = BN(x + head @ wo^T + bo) -> fp32 x + fp16 xh
        hgemm<128, TCE_BN, true><<<dim3(8, 32), 256, SM128>>>(
            phd16, pwoh + (size_t)l*Dm*DKh, bo + l*Dm, DKh, 1.f, px, Dm, pxh,
            nullptr, nullptr, 0, 0, 0,
            px, ag + l*Dm, ab + l*Dm, am + l*Dm, avv + l*Dm);

        if (l == 0) cudaStreamWaitEvent(0, evW1, 0);

        // h = relu(x @ w1^T + b1) -> fp16
        hgemm<128, TCE_RELU, false><<<dim3(FFd/128, 32), 256, SM128>>>(
            pxh, pw1h + (size_t)l*FFd*Dm, b1 + l*FFd, Dm, 1.f,
            nullptr, FFd, ph16, nullptr, nullptr, 0, 0, 0,
            nullptr, nullptr, nullptr, nullptr, nullptr);

        if (l == 0) cudaStreamWaitEvent(0, evW2, 0);

        // x = BN(x + h @ w2^T + b2)
        if (l < NL-1) {
            hgemm<128, TCE_BN, true><<<dim3(Dm/128, 32), 256, SM128>>>(
                ph16, pw2h + (size_t)l*Dm*FFd, b2 + l*Dm, FFd, 1.f, px, Dm, pxh,
                nullptr, nullptr, 0, 0, 0,
                px, fg + l*Dm, fb + l*Dm, fm + l*Dm, fv + l*Dm);
        } else {
            hgemm<128, TCE_BN, false><<<dim3(Dm/128, 32), 256, SM128>>>(
                ph16, pw2h + (size_t)l*Dm*FFd, b2 + l*Dm, FFd, 1.f, out, Dm, nullptr,
                nullptr, nullptr, 0, 0, 0,
                px, fg + l*Dm, fb + l*Dm, fm + l*Dm, fv + l*Dm);
        }
    }
}